// round 9
// baseline (speedup 1.0000x reference)
#include <cuda_runtime.h>
#include <cuda_bf16.h>
#include <math.h>

#define BATCH 4
#define SEQ   4096
#define DIN   1024
#define DH    64
#define PAD   68   // qkv_gemm only

typedef unsigned int u32;

// bf16 hi/lo split scratch (written by qkv_gemm, read by flash_attn_mma)
__device__ __nv_bfloat16 g_Qh[BATCH * SEQ * DH];
__device__ __nv_bfloat16 g_Ql[BATCH * SEQ * DH];
__device__ __nv_bfloat16 g_Kh[BATCH * SEQ * DH];
__device__ __nv_bfloat16 g_Kl[BATCH * SEQ * DH];
__device__ __nv_bfloat16 g_Vth[BATCH * DH * SEQ];  // transposed: [b][d][s]
__device__ __nv_bfloat16 g_Vtl[BATCH * DH * SEQ];

__device__ __forceinline__ u32 smem_u32(const void* p) {
    u32 a;
    asm("{ .reg .u64 t; cvta.to.shared.u64 t, %1; cvt.u32.u64 %0, t; }"
        : "=r"(a) : "l"(p));
    return a;
}
__device__ __forceinline__ float ex2f(float x) {
    float r;
    asm("ex2.approx.ftz.f32 %0, %1;" : "=f"(r) : "f"(x));
    return r;
}
__device__ __forceinline__ u32 bfpack(__nv_bfloat16 a, __nv_bfloat16 b) {
    __nv_bfloat162 v; v.x = a; v.y = b;
    return *(u32*)&v;
}
__device__ __forceinline__ u32 packsplit(float x, float y, u32& lo) {
    __nv_bfloat16 hx = __float2bfloat16(x), hy = __float2bfloat16(y);
    lo = bfpack(__float2bfloat16(x - __bfloat162float(hx)),
                __float2bfloat16(y - __bfloat162float(hy)));
    return bfpack(hx, hy);
}
__device__ __forceinline__ void mma_bf16(float c[4], const u32 a[4], u32 b0, u32 b1) {
    asm volatile(
        "mma.sync.aligned.m16n8k16.row.col.f32.bf16.bf16.f32 "
        "{%0,%1,%2,%3}, {%4,%5,%6,%7}, {%8,%9}, {%0,%1,%2,%3};"
        : "+f"(c[0]), "+f"(c[1]), "+f"(c[2]), "+f"(c[3])
        : "r"(a[0]), "r"(a[1]), "r"(a[2]), "r"(a[3]), "r"(b0), "r"(b1));
}
__device__ __forceinline__ void ldm4(u32* r, u32 a) {
    asm volatile("ldmatrix.sync.aligned.m8n8.x4.shared.b16 {%0,%1,%2,%3}, [%4];"
        : "=r"(r[0]), "=r"(r[1]), "=r"(r[2]), "=r"(r[3]) : "r"(a));
}
__device__ __forceinline__ void cp16(u32 s, const void* g) {
    asm volatile("cp.async.cg.shared.global [%0], [%1], 16;" :: "r"(s), "l"(g) : "memory");
}
#define CP_COMMIT() asm volatile("cp.async.commit_group;" ::: "memory")
#define CP_WAIT0()  asm volatile("cp.async.wait_group 0;" ::: "memory")

// ---------------------------------------------------------------------------
// QKV projection GEMM (fp32 scalar) + bf16 hi/lo split epilogue.
// ---------------------------------------------------------------------------
__global__ __launch_bounds__(256) void qkv_gemm(const float* __restrict__ X,
                                                const float* __restrict__ Wq,
                                                const float* __restrict__ Wk,
                                                const float* __restrict__ Wv) {
    __shared__ float Xs[64][17];
    __shared__ float Ws[16][PAD];

    const float* W = (blockIdx.y == 0) ? Wq : (blockIdx.y == 1) ? Wk : Wv;

    const int tid  = threadIdx.x;
    const int row0 = blockIdx.x * 64;
    const int tx   = tid & 15;
    const int ty   = tid >> 4;

    float acc[4][4];
#pragma unroll
    for (int i = 0; i < 4; i++)
#pragma unroll
        for (int j = 0; j < 4; j++) acc[i][j] = 0.f;

    for (int k0 = 0; k0 < DIN; k0 += 16) {
        {
            int r = tid >> 2, c4 = tid & 3;
            float4 v = *(const float4*)(X + (size_t)(row0 + r) * DIN + k0 + c4 * 4);
            Xs[r][c4 * 4 + 0] = v.x; Xs[r][c4 * 4 + 1] = v.y;
            Xs[r][c4 * 4 + 2] = v.z; Xs[r][c4 * 4 + 3] = v.w;
        }
        {
            int r = tid >> 4, c4 = tid & 15;
            float4 v = *(const float4*)(W + (size_t)(k0 + r) * DH + c4 * 4);
            *(float4*)&Ws[r][c4 * 4] = v;
        }
        __syncthreads();

#pragma unroll
        for (int kk = 0; kk < 16; kk++) {
            float a[4];
#pragma unroll
            for (int i = 0; i < 4; i++) a[i] = Xs[ty * 4 + i][kk];
            float4 b4 = *(float4*)&Ws[kk][tx * 4];
            float b[4] = {b4.x, b4.y, b4.z, b4.w};
#pragma unroll
            for (int i = 0; i < 4; i++)
#pragma unroll
                for (int j = 0; j < 4; j++) acc[i][j] = fmaf(a[i], b[j], acc[i][j]);
        }
        __syncthreads();
    }

    if (blockIdx.y < 2) {
        const float qs = (blockIdx.y == 0) ? (0.125f * 1.44269504088896340736f) : 1.f;
        u32* H = (u32*)((blockIdx.y == 0) ? g_Qh : g_Kh);
        u32* L = (u32*)((blockIdx.y == 0) ? g_Ql : g_Kl);
#pragma unroll
        for (int i = 0; i < 4; i++) {
            u32 lo0, lo1;
            u32 h0 = packsplit(acc[i][0] * qs, acc[i][1] * qs, lo0);
            u32 h1 = packsplit(acc[i][2] * qs, acc[i][3] * qs, lo1);
            size_t idx = (size_t)(row0 + ty * 4 + i) * 32 + tx * 2;
            H[idx] = h0; H[idx + 1] = h1;
            L[idx] = lo0; L[idx + 1] = lo1;
        }
    } else {
        u32* H = (u32*)g_Vth;
        u32* L = (u32*)g_Vtl;
        const int b    = row0 >> 12;
        const int tok0 = (row0 & (SEQ - 1)) + ty * 4;
#pragma unroll
        for (int j = 0; j < 4; j++) {
            const int d = tx * 4 + j;
            u32 lo0, lo1;
            u32 h0 = packsplit(acc[0][j], acc[1][j], lo0);
            u32 h1 = packsplit(acc[2][j], acc[3][j], lo1);
            size_t idx = ((size_t)b * 64 + d) * (SEQ / 2) + (tok0 >> 1);
            H[idx] = h0; H[idx + 1] = h1;
            L[idx] = lo0; L[idx + 1] = lo1;
        }
    }
}

// ---------------------------------------------------------------------------
// Double-buffered cp.async prefetch of one kv tile. Warp w fills buffer
// (t&1)*4 + w. Buffers: 0=Kh 1=Kl 2=Vth 3=Vtl. Rows = 32 u32 words (128B),
// 16B chunk c of row r stored at chunk c ^ (r & 7).
// ---------------------------------------------------------------------------
__device__ __forceinline__ void prefetch_tile(int t, int b, int w, int lane, u32 sb0) {
    const int j0 = t * 64;
    const u32* src; size_t rstride;
    if (w == 0)      { src = (const u32*)g_Kh  + ((size_t)b * SEQ + j0) * 32; rstride = 32; }
    else if (w == 1) { src = (const u32*)g_Kl  + ((size_t)b * SEQ + j0) * 32; rstride = 32; }
    else if (w == 2) { src = (const u32*)g_Vth + (size_t)b * 64 * (SEQ / 2) + j0 / 2; rstride = SEQ / 2; }
    else             { src = (const u32*)g_Vtl + (size_t)b * 64 * (SEQ / 2) + j0 / 2; rstride = SEQ / 2; }
    const u32 dst = sb0 + (u32)(((t & 1) * 4 + w) * 8192);
#pragma unroll
    for (int rr = 0; rr < 2; rr++) {
        const int r = lane * 2 + rr;
        const u32* s = src + (size_t)r * rstride;
        const u32 da = dst + (u32)(r * 128);
        const int sw = r & 7;
#pragma unroll
        for (int c = 0; c < 8; c++)
            cp16(da + (u32)(((c ^ sw)) << 4), s + c * 4);
    }
    CP_COMMIT();
}

// ---------------------------------------------------------------------------
// HMMA bf16-split causal flash attention, ldmatrix fragments, cp.async
// double-buffered K/V. 256 CTAs x 128 threads; warp w owns m16 rows 16w..+15.
// smem (dynamic 64 KB): 8 buffers of 8 KB (two sets of Kh/Kl/Vth/Vtl);
// buffers 4,5 double as the one-time Q staging area before tile 1 lands.
// ---------------------------------------------------------------------------
__global__ __launch_bounds__(128, 2) void flash_attn_mma(float* __restrict__ O) {
    extern __shared__ __align__(16) u32 sdyn[];
    const u32 sb0 = smem_u32(sdyn);

    // Balanced causal schedule: bid and bid+148 share an SM, tiles sum to 65.
    const int bid = blockIdx.x;
    int qt, b;
    if (bid < 148) { qt = 63 - (bid >> 2); b = bid & 3; }
    else           { qt = (bid - 148) >> 2; b = (bid - 148) & 3; }

    const int tid   = threadIdx.x;
    const int w     = tid >> 5;
    const int lane  = tid & 31;
    const int lane7 = lane & 7;
    const int g     = lane >> 2;
    const int t4    = lane & 3;
    const int i0    = qt * 64;

    // ---- Prefetch kv tile 0 (overlaps Q staging) ----
    prefetch_tile(0, b, w, lane, sb0);

    // ---- Stage Q (hi/lo) into buffers 4,5 ----
    if (w < 2) {
        const u32* src = (const u32*)(w == 0 ? g_Qh : g_Ql) + (size_t)(b * SEQ + i0) * 32;
        u32* dstp = sdyn + (4 + w) * 2048;
#pragma unroll
        for (int rr = 0; rr < 2; rr++) {
            const int r = lane * 2 + rr;
            const u32* s = src + r * 32;
#pragma unroll
            for (int c = 0; c < 8; c++)
                *(uint4*)(dstp + r * 32 + ((c ^ (r & 7)) << 2)) = *(const uint4*)(s + c * 4);
        }
    }
    __syncthreads();

    // ---- Extract Q A-fragments via ldmatrix (8 instrs) ----
    u32 qh[4][4], ql[4][4];
    {
        const int m  = lane >> 3, rr = lane & 7;
        const int qrow = 16 * w + rr + 8 * (m & 1);
        const u32 qbh = sb0 + 4u * 8192 + (u32)(qrow * 128);
        const u32 qbl = sb0 + 5u * 8192 + (u32)(qrow * 128);
#pragma unroll
        for (int ks = 0; ks < 4; ks++) {
            const u32 off = (u32)(((2 * ks + (m >> 1)) ^ rr) << 4);
            ldm4(qh[ks], qbh + off);
            ldm4(ql[ks], qbl + off);
        }
    }

    float o[8][4];
#pragma unroll
    for (int nb = 0; nb < 8; nb++)
#pragma unroll
        for (int e = 0; e < 4; e++) o[nb][e] = 0.f;
    float lacc0 = 0.f, lacc1 = 0.f;

    const u32 rowoff = (u32)(lane * 128);

    for (int t = 0; t <= qt; t++) {
        const int j0 = t * 64;
        const int pb4 = (t & 1) * 4;

        CP_WAIT0();            // this warp's tile-t copies complete
        __syncthreads();       // all buffers ready; all warps done with t-1
        if (t < qt) prefetch_tile(t + 1, b, w, lane, sb0);

        const u32 bKh = sb0 + (u32)((pb4 + 0) * 8192) + rowoff;
        const u32 bKl = sb0 + (u32)((pb4 + 1) * 8192) + rowoff;
        const u32 bVh = sb0 + (u32)((pb4 + 2) * 8192) + rowoff;
        const u32 bVl = sb0 + (u32)((pb4 + 3) * 8192) + rowoff;

        // ---- S = Qh·Kh + Ql·Kh + Qh·Kl ----
        float s[8][4];
#pragma unroll
        for (int nb = 0; nb < 8; nb++)
#pragma unroll
            for (int e = 0; e < 4; e++) s[nb][e] = 0.f;

#pragma unroll
        for (int ks = 0; ks < 4; ks++) {
            const u32 c0 = (u32)(((2 * ks)     ^ lane7) << 4);
            const u32 c1 = (u32)(((2 * ks + 1) ^ lane7) << 4);
            u32 f[16];
            ldm4(f,      bKh + c0);
            ldm4(f + 4,  bKh + c1);
            ldm4(f + 8,  bKh + 4096 + c0);
            ldm4(f + 12, bKh + 4096 + c1);
#pragma unroll
            for (int nb = 0; nb < 4; nb++) {
                mma_bf16(s[nb],     qh[ks], f[nb],     f[4 + nb]);
                mma_bf16(s[nb],     ql[ks], f[nb],     f[4 + nb]);
                mma_bf16(s[4 + nb], qh[ks], f[8 + nb], f[12 + nb]);
                mma_bf16(s[4 + nb], ql[ks], f[8 + nb], f[12 + nb]);
            }
            u32 gf[16];
            ldm4(gf,      bKl + c0);
            ldm4(gf + 4,  bKl + c1);
            ldm4(gf + 8,  bKl + 4096 + c0);
            ldm4(gf + 12, bKl + 4096 + c1);
#pragma unroll
            for (int nb = 0; nb < 4; nb++) {
                mma_bf16(s[nb],     qh[ks], gf[nb],     gf[4 + nb]);
                mma_bf16(s[4 + nb], qh[ks], gf[8 + nb], gf[12 + nb]);
            }
        }

        // ---- Fixed-max softmax + causal mask on the diagonal tile ----
        const bool diag = (t == qt);
        const int rowa = i0 + 16 * w + g;
        const int rowb = rowa + 8;
#pragma unroll
        for (int nb = 0; nb < 8; nb++) {
            const int colb = j0 + 8 * nb + 2 * t4;
            float p0 = ex2f(s[nb][0]); if (diag && colb     > rowa) p0 = 0.f;
            float p1 = ex2f(s[nb][1]); if (diag && colb + 1 > rowa) p1 = 0.f;
            float p2 = ex2f(s[nb][2]); if (diag && colb     > rowb) p2 = 0.f;
            float p3 = ex2f(s[nb][3]); if (diag && colb + 1 > rowb) p3 = 0.f;
            lacc0 += p0 + p1;
            lacc1 += p2 + p3;
            s[nb][0] = p0; s[nb][1] = p1; s[nb][2] = p2; s[nb][3] = p3;
        }

        // ---- P -> bf16 hi/lo A-fragments (registers only) ----
        u32 ph[4][4], pl[4][4];
#pragma unroll
        for (int ks = 0; ks < 4; ks++) {
            ph[ks][0] = packsplit(s[2 * ks][0],     s[2 * ks][1],     pl[ks][0]);
            ph[ks][1] = packsplit(s[2 * ks][2],     s[2 * ks][3],     pl[ks][1]);
            ph[ks][2] = packsplit(s[2 * ks + 1][0], s[2 * ks + 1][1], pl[ks][2]);
            ph[ks][3] = packsplit(s[2 * ks + 1][2], s[2 * ks + 1][3], pl[ks][3]);
        }

        // ---- O += Ph·Vh + Pl·Vh + Ph·Vl ----
#pragma unroll
        for (int ks = 0; ks < 4; ks++) {
            const u32 c0 = (u32)(((2 * ks)     ^ lane7) << 4);
            const u32 c1 = (u32)(((2 * ks + 1) ^ lane7) << 4);
            u32 f[16];
            ldm4(f,      bVh + c0);
            ldm4(f + 4,  bVh + c1);
            ldm4(f + 8,  bVh + 4096 + c0);
            ldm4(f + 12, bVh + 4096 + c1);
#pragma unroll
            for (int nb = 0; nb < 4; nb++) {
                mma_bf16(o[nb],     ph[ks], f[nb],     f[4 + nb]);
                mma_bf16(o[nb],     pl[ks], f[nb],     f[4 + nb]);
                mma_bf16(o[4 + nb], ph[ks], f[8 + nb], f[12 + nb]);
                mma_bf16(o[4 + nb], pl[ks], f[8 + nb], f[12 + nb]);
            }
            u32 gf[16];
            ldm4(gf,      bVl + c0);
            ldm4(gf + 4,  bVl + c1);
            ldm4(gf + 8,  bVl + 4096 + c0);
            ldm4(gf + 12, bVl + 4096 + c1);
#pragma unroll
            for (int nb = 0; nb < 4; nb++) {
                mma_bf16(o[nb],     ph[ks], gf[nb],     gf[4 + nb]);
                mma_bf16(o[4 + nb], ph[ks], gf[8 + nb], gf[12 + nb]);
            }
        }
    }

    // ---- Reduce l, normalize, store ----
    lacc0 += __shfl_xor_sync(0xffffffffu, lacc0, 1);
    lacc0 += __shfl_xor_sync(0xffffffffu, lacc0, 2);
    lacc1 += __shfl_xor_sync(0xffffffffu, lacc1, 1);
    lacc1 += __shfl_xor_sync(0xffffffffu, lacc1, 2);
    const float inv0 = 1.f / lacc0;
    const float inv1 = 1.f / lacc1;

    const size_t r0g = (size_t)b * SEQ + i0 + 16 * w + g;
#pragma unroll
    for (int nb = 0; nb < 8; nb++) {
        float2 v0 = make_float2(o[nb][0] * inv0, o[nb][1] * inv0);
        float2 v1 = make_float2(o[nb][2] * inv1, o[nb][3] * inv1);
        *(float2*)(O + r0g * 64 + 8 * nb + 2 * t4)       = v0;
        *(float2*)(O + (r0g + 8) * 64 + 8 * nb + 2 * t4) = v1;
    }
}

// ---------------------------------------------------------------------------
extern "C" void kernel_launch(void* const* d_in, const int* in_sizes, int n_in,
                              void* d_out, int out_size) {
    const float* X  = (const float*)d_in[0];
    const float* Wq = (const float*)d_in[1];
    const float* Wk = (const float*)d_in[2];
    const float* Wv = (const float*)d_in[3];
    float* O = (float*)d_out;

    static int attr_set = 0;
    if (!attr_set) {
        cudaFuncSetAttribute(flash_attn_mma,
                             cudaFuncAttributeMaxDynamicSharedMemorySize, 65536);
        attr_set = 1;
    }

    dim3 gproj((BATCH * SEQ) / 64, 3);
    qkv_gemm<<<gproj, 256>>>(X, Wq, Wk, Wv);

    flash_attn_mma<<<256, 128, 65536>>>(O);
}

// round 10
// speedup vs baseline: 1.4011x; 1.4011x over previous
#include <cuda_runtime.h>
#include <cuda_bf16.h>
#include <math.h>

#define BATCH 4
#define SEQ   4096
#define DIN   1024
#define DH    64
#define PAD   68   // qkv_gemm only

typedef unsigned int u32;

// bf16 hi/lo split scratch (written by qkv_gemm, read by flash_attn_mma)
__device__ __nv_bfloat16 g_Qh[BATCH * SEQ * DH];
__device__ __nv_bfloat16 g_Ql[BATCH * SEQ * DH];
__device__ __nv_bfloat16 g_Kh[BATCH * SEQ * DH];
__device__ __nv_bfloat16 g_Kl[BATCH * SEQ * DH];
__device__ __nv_bfloat16 g_Vth[BATCH * DH * SEQ];  // transposed: [b][d][s]
__device__ __nv_bfloat16 g_Vtl[BATCH * DH * SEQ];

__device__ __forceinline__ u32 smem_u32(const void* p) {
    u32 a;
    asm("{ .reg .u64 t; cvta.to.shared.u64 t, %1; cvt.u32.u64 %0, t; }"
        : "=r"(a) : "l"(p));
    return a;
}
__device__ __forceinline__ float ex2f(float x) {
    float r;
    asm("ex2.approx.ftz.f32 %0, %1;" : "=f"(r) : "f"(x));
    return r;
}
__device__ __forceinline__ u32 bfpack(__nv_bfloat16 a, __nv_bfloat16 b) {
    __nv_bfloat162 v; v.x = a; v.y = b;
    return *(u32*)&v;
}
__device__ __forceinline__ u32 packsplit(float x, float y, u32& lo) {
    __nv_bfloat16 hx = __float2bfloat16(x), hy = __float2bfloat16(y);
    lo = bfpack(__float2bfloat16(x - __bfloat162float(hx)),
                __float2bfloat16(y - __bfloat162float(hy)));
    return bfpack(hx, hy);
}
__device__ __forceinline__ void mma_bf16(float c[4], const u32 a[4], u32 b0, u32 b1) {
    asm volatile(
        "mma.sync.aligned.m16n8k16.row.col.f32.bf16.bf16.f32 "
        "{%0,%1,%2,%3}, {%4,%5,%6,%7}, {%8,%9}, {%0,%1,%2,%3};"
        : "+f"(c[0]), "+f"(c[1]), "+f"(c[2]), "+f"(c[3])
        : "r"(a[0]), "r"(a[1]), "r"(a[2]), "r"(a[3]), "r"(b0), "r"(b1));
}
__device__ __forceinline__ void ldm4(u32* r, u32 a) {
    asm volatile("ldmatrix.sync.aligned.m8n8.x4.shared.b16 {%0,%1,%2,%3}, [%4];"
        : "=r"(r[0]), "=r"(r[1]), "=r"(r[2]), "=r"(r[3]) : "r"(a));
}

// ---------------------------------------------------------------------------
// QKV projection GEMM (fp32 scalar) + bf16 hi/lo split epilogue.
// ---------------------------------------------------------------------------
__global__ __launch_bounds__(256) void qkv_gemm(const float* __restrict__ X,
                                                const float* __restrict__ Wq,
                                                const float* __restrict__ Wk,
                                                const float* __restrict__ Wv) {
    __shared__ float Xs[64][17];
    __shared__ float Ws[16][PAD];

    const float* W = (blockIdx.y == 0) ? Wq : (blockIdx.y == 1) ? Wk : Wv;

    const int tid  = threadIdx.x;
    const int row0 = blockIdx.x * 64;
    const int tx   = tid & 15;
    const int ty   = tid >> 4;

    float acc[4][4];
#pragma unroll
    for (int i = 0; i < 4; i++)
#pragma unroll
        for (int j = 0; j < 4; j++) acc[i][j] = 0.f;

    for (int k0 = 0; k0 < DIN; k0 += 16) {
        {
            int r = tid >> 2, c4 = tid & 3;
            float4 v = *(const float4*)(X + (size_t)(row0 + r) * DIN + k0 + c4 * 4);
            Xs[r][c4 * 4 + 0] = v.x; Xs[r][c4 * 4 + 1] = v.y;
            Xs[r][c4 * 4 + 2] = v.z; Xs[r][c4 * 4 + 3] = v.w;
        }
        {
            int r = tid >> 4, c4 = tid & 15;
            float4 v = *(const float4*)(W + (size_t)(k0 + r) * DH + c4 * 4);
            *(float4*)&Ws[r][c4 * 4] = v;
        }
        __syncthreads();

#pragma unroll
        for (int kk = 0; kk < 16; kk++) {
            float a[4];
#pragma unroll
            for (int i = 0; i < 4; i++) a[i] = Xs[ty * 4 + i][kk];
            float4 b4 = *(float4*)&Ws[kk][tx * 4];
            float b[4] = {b4.x, b4.y, b4.z, b4.w};
#pragma unroll
            for (int i = 0; i < 4; i++)
#pragma unroll
                for (int j = 0; j < 4; j++) acc[i][j] = fmaf(a[i], b[j], acc[i][j]);
        }
        __syncthreads();
    }

    if (blockIdx.y < 2) {
        const float qs = (blockIdx.y == 0) ? (0.125f * 1.44269504088896340736f) : 1.f;
        u32* H = (u32*)((blockIdx.y == 0) ? g_Qh : g_Kh);
        u32* L = (u32*)((blockIdx.y == 0) ? g_Ql : g_Kl);
#pragma unroll
        for (int i = 0; i < 4; i++) {
            u32 lo0, lo1;
            u32 h0 = packsplit(acc[i][0] * qs, acc[i][1] * qs, lo0);
            u32 h1 = packsplit(acc[i][2] * qs, acc[i][3] * qs, lo1);
            size_t idx = (size_t)(row0 + ty * 4 + i) * 32 + tx * 2;
            H[idx] = h0; H[idx + 1] = h1;
            L[idx] = lo0; L[idx + 1] = lo1;
        }
    } else {
        u32* H = (u32*)g_Vth;
        u32* L = (u32*)g_Vtl;
        const int b    = row0 >> 12;
        const int tok0 = (row0 & (SEQ - 1)) + ty * 4;
#pragma unroll
        for (int j = 0; j < 4; j++) {
            const int d = tx * 4 + j;
            u32 lo0, lo1;
            u32 h0 = packsplit(acc[0][j], acc[1][j], lo0);
            u32 h1 = packsplit(acc[2][j], acc[3][j], lo1);
            size_t idx = ((size_t)b * 64 + d) * (SEQ / 2) + (tok0 >> 1);
            H[idx] = h0; H[idx + 1] = h1;
            L[idx] = lo0; L[idx + 1] = lo1;
        }
    }
}

// ---------------------------------------------------------------------------
// HMMA bf16-split causal flash attention (R8 data movement + ldmatrix
// fragment loads). 256 CTAs x 128 threads; warp w owns m16 rows 16w..+15.
// smem: 4 static buffers (Kh, Kl, Vth, Vtl) 64x64 bf16, chunk-XOR swizzled
// (16B chunk c of row r stored at chunk c ^ (r & 7); rows = 128 B).
// ---------------------------------------------------------------------------
__global__ __launch_bounds__(128, 2) void flash_attn_mma(float* __restrict__ O) {
    __shared__ u32 sbuf[4][2048];   // 4 x 8 KB
    const u32 sb0 = smem_u32(sbuf);

    // Balanced causal schedule: bid and bid+148 share an SM, tiles sum to 65.
    const int bid = blockIdx.x;
    int qt, b;
    if (bid < 148) { qt = 63 - (bid >> 2); b = bid & 3; }
    else           { qt = (bid - 148) >> 2; b = (bid - 148) & 3; }

    const int tid   = threadIdx.x;
    const int w     = tid >> 5;
    const int lane  = tid & 31;
    const int lane7 = lane & 7;
    const int g     = lane >> 2;
    const int t4    = lane & 3;
    const int i0    = qt * 64;

    // ---- Stage Q tile (hi/lo) into sbuf[0..1] ----
    if (w < 2) {
        const u32* src = (const u32*)(w == 0 ? g_Qh : g_Ql) + (size_t)(b * SEQ + i0) * 32;
        u32* dst = &sbuf[w][0];
#pragma unroll
        for (int rr = 0; rr < 2; rr++) {
            const int r = lane * 2 + rr;
            const u32* s = src + r * 32;
#pragma unroll
            for (int c = 0; c < 8; c++) {
                uint4 v = *(const uint4*)(s + c * 4);
                *(uint4*)(dst + r * 32 + ((c ^ (r & 7)) << 2)) = v;
            }
        }
    }
    __syncthreads();

    // ---- Extract Q A-fragments via ldmatrix (mapping verified in R9) ----
    u32 qh[4][4], ql[4][4];
    {
        const int m  = lane >> 3, rr = lane & 7;
        const int qrow = 16 * w + rr + 8 * (m & 1);
        const u32 qbh = sb0 + (u32)(qrow * 128);
        const u32 qbl = sb0 + 8192u + (u32)(qrow * 128);
#pragma unroll
        for (int ks = 0; ks < 4; ks++) {
            const u32 off = (u32)(((2 * ks + (m >> 1)) ^ rr) << 4);
            ldm4(qh[ks], qbh + off);
            ldm4(ql[ks], qbl + off);
        }
    }
    __syncthreads();

    float o[8][4];
#pragma unroll
    for (int nb = 0; nb < 8; nb++)
#pragma unroll
        for (int e = 0; e < 4; e++) o[nb][e] = 0.f;
    float lacc0 = 0.f, lacc1 = 0.f;

    const u32 rowoff = (u32)(lane * 128);
    const u32 bKh = sb0 + rowoff;
    const u32 bKl = sb0 + 8192u + rowoff;
    const u32 bVh = sb0 + 16384u + rowoff;
    const u32 bVl = sb0 + 24576u + rowoff;

    for (int t = 0; t <= qt; t++) {
        const int j0 = t * 64;

        // ---- Load tiles: warp w fills buffer w (LDG + swizzled STS) ----
        {
            const u32* src; size_t rstride;
            if (w == 0)      { src = (const u32*)g_Kh  + ((size_t)b * SEQ + j0) * 32; rstride = 32; }
            else if (w == 1) { src = (const u32*)g_Kl  + ((size_t)b * SEQ + j0) * 32; rstride = 32; }
            else if (w == 2) { src = (const u32*)g_Vth + (size_t)b * 64 * (SEQ / 2) + j0 / 2; rstride = SEQ / 2; }
            else             { src = (const u32*)g_Vtl + (size_t)b * 64 * (SEQ / 2) + j0 / 2; rstride = SEQ / 2; }
            u32* dst = &sbuf[w][0];
#pragma unroll
            for (int rr = 0; rr < 2; rr++) {
                const int r = lane * 2 + rr;
                const u32* s = src + (size_t)r * rstride;
#pragma unroll
                for (int c = 0; c < 8; c++) {
                    uint4 v = *(const uint4*)(s + c * 4);
                    *(uint4*)(dst + r * 32 + ((c ^ (r & 7)) << 2)) = v;
                }
            }
        }
        __syncthreads();

        // ---- S = Qh·Kh + Ql·Kh + Qh·Kl (ldmatrix B-fragments) ----
        float s[8][4];
#pragma unroll
        for (int nb = 0; nb < 8; nb++)
#pragma unroll
            for (int e = 0; e < 4; e++) s[nb][e] = 0.f;

#pragma unroll
        for (int ks = 0; ks < 4; ks++) {
            const u32 c0 = (u32)(((2 * ks)     ^ lane7) << 4);
            const u32 c1 = (u32)(((2 * ks + 1) ^ lane7) << 4);
            u32 f[16];
            ldm4(f,      bKh + c0);
            ldm4(f + 4,  bKh + c1);
            ldm4(f + 8,  bKh + 4096 + c0);
            ldm4(f + 12, bKh + 4096 + c1);
#pragma unroll
            for (int nb = 0; nb < 4; nb++) {
                mma_bf16(s[nb],     qh[ks], f[nb],     f[4 + nb]);
                mma_bf16(s[nb],     ql[ks], f[nb],     f[4 + nb]);
                mma_bf16(s[4 + nb], qh[ks], f[8 + nb], f[12 + nb]);
                mma_bf16(s[4 + nb], ql[ks], f[8 + nb], f[12 + nb]);
            }
            u32 gf[16];
            ldm4(gf,      bKl + c0);
            ldm4(gf + 4,  bKl + c1);
            ldm4(gf + 8,  bKl + 4096 + c0);
            ldm4(gf + 12, bKl + 4096 + c1);
#pragma unroll
            for (int nb = 0; nb < 4; nb++) {
                mma_bf16(s[nb],     qh[ks], gf[nb],     gf[4 + nb]);
                mma_bf16(s[4 + nb], qh[ks], gf[8 + nb], gf[12 + nb]);
            }
        }

        // ---- Fixed-max softmax + causal mask on the diagonal tile ----
        const bool diag = (t == qt);
        const int rowa = i0 + 16 * w + g;
        const int rowb = rowa + 8;
#pragma unroll
        for (int nb = 0; nb < 8; nb++) {
            const int colb = j0 + 8 * nb + 2 * t4;
            float p0 = ex2f(s[nb][0]); if (diag && colb     > rowa) p0 = 0.f;
            float p1 = ex2f(s[nb][1]); if (diag && colb + 1 > rowa) p1 = 0.f;
            float p2 = ex2f(s[nb][2]); if (diag && colb     > rowb) p2 = 0.f;
            float p3 = ex2f(s[nb][3]); if (diag && colb + 1 > rowb) p3 = 0.f;
            lacc0 += p0 + p1;
            lacc1 += p2 + p3;
            s[nb][0] = p0; s[nb][1] = p1; s[nb][2] = p2; s[nb][3] = p3;
        }

        // ---- P -> bf16 hi/lo A-fragments (registers only) ----
        u32 ph[4][4], pl[4][4];
#pragma unroll
        for (int ks = 0; ks < 4; ks++) {
            ph[ks][0] = packsplit(s[2 * ks][0],     s[2 * ks][1],     pl[ks][0]);
            ph[ks][1] = packsplit(s[2 * ks][2],     s[2 * ks][3],     pl[ks][1]);
            ph[ks][2] = packsplit(s[2 * ks + 1][0], s[2 * ks + 1][1], pl[ks][2]);
            ph[ks][3] = packsplit(s[2 * ks + 1][2], s[2 * ks + 1][3], pl[ks][3]);
        }

        // ---- O += Ph·Vh + Pl·Vh + Ph·Vl ----
#pragma unroll
        for (int ks = 0; ks < 4; ks++) {
            const u32 c0 = (u32)(((2 * ks)     ^ lane7) << 4);
            const u32 c1 = (u32)(((2 * ks + 1) ^ lane7) << 4);
            u32 f[16];
            ldm4(f,      bVh + c0);
            ldm4(f + 4,  bVh + c1);
            ldm4(f + 8,  bVh + 4096 + c0);
            ldm4(f + 12, bVh + 4096 + c1);
#pragma unroll
            for (int nb = 0; nb < 4; nb++) {
                mma_bf16(o[nb],     ph[ks], f[nb],     f[4 + nb]);
                mma_bf16(o[nb],     pl[ks], f[nb],     f[4 + nb]);
                mma_bf16(o[4 + nb], ph[ks], f[8 + nb], f[12 + nb]);
                mma_bf16(o[4 + nb], pl[ks], f[8 + nb], f[12 + nb]);
            }
            u32 gf[16];
            ldm4(gf,      bVl + c0);
            ldm4(gf + 4,  bVl + c1);
            ldm4(gf + 8,  bVl + 4096 + c0);
            ldm4(gf + 12, bVl + 4096 + c1);
#pragma unroll
            for (int nb = 0; nb < 4; nb++) {
                mma_bf16(o[nb],     ph[ks], gf[nb],     gf[4 + nb]);
                mma_bf16(o[4 + nb], ph[ks], gf[8 + nb], gf[12 + nb]);
            }
        }
        __syncthreads();   // PV readers done before next tile's loader writes
    }

    // ---- Reduce l, normalize, store ----
    lacc0 += __shfl_xor_sync(0xffffffffu, lacc0, 1);
    lacc0 += __shfl_xor_sync(0xffffffffu, lacc0, 2);
    lacc1 += __shfl_xor_sync(0xffffffffu, lacc1, 1);
    lacc1 += __shfl_xor_sync(0xffffffffu, lacc1, 2);
    const float inv0 = 1.f / lacc0;
    const float inv1 = 1.f / lacc1;

    const size_t r0g = (size_t)b * SEQ + i0 + 16 * w + g;
#pragma unroll
    for (int nb = 0; nb < 8; nb++) {
        float2 v0 = make_float2(o[nb][0] * inv0, o[nb][1] * inv0);
        float2 v1 = make_float2(o[nb][2] * inv1, o[nb][3] * inv1);
        *(float2*)(O + r0g * 64 + 8 * nb + 2 * t4)       = v0;
        *(float2*)(O + (r0g + 8) * 64 + 8 * nb + 2 * t4) = v1;
    }
}

// ---------------------------------------------------------------------------
extern "C" void kernel_launch(void* const* d_in, const int* in_sizes, int n_in,
                              void* d_out, int out_size) {
    const float* X  = (const float*)d_in[0];
    const float* Wq = (const float*)d_in[1];
    const float* Wk = (const float*)d_in[2];
    const float* Wv = (const float*)d_in[3];
    float* O = (float*)d_out;

    dim3 gproj((BATCH * SEQ) / 64, 3);
    qkv_gemm<<<gproj, 256>>>(X, Wq, Wk, Wv);

    flash_attn_mma<<<256, 128>>>(O);
}

// round 11
// speedup vs baseline: 1.9325x; 1.3792x over previous
#include <cuda_runtime.h>
#include <cuda_bf16.h>
#include <math.h>

#define BATCH 4
#define SEQ   4096
#define DIN   1024
#define DH    64

typedef unsigned int u32;

// bf16 hi/lo split scratch
__device__ __nv_bfloat16 g_Qh[BATCH * SEQ * DH];
__device__ __nv_bfloat16 g_Ql[BATCH * SEQ * DH];
__device__ __nv_bfloat16 g_Kh[BATCH * SEQ * DH];
__device__ __nv_bfloat16 g_Kl[BATCH * SEQ * DH];
__device__ __nv_bfloat16 g_Vth[BATCH * DH * SEQ];  // transposed: [b][d][s]
__device__ __nv_bfloat16 g_Vtl[BATCH * DH * SEQ];
// W transposed+split: [mat][n][k] bf16 (B-tile layout identical to K tiles)
__device__ __nv_bfloat16 g_Wh[3 * DH * DIN];
__device__ __nv_bfloat16 g_Wl[3 * DH * DIN];

__device__ __forceinline__ u32 smem_u32(const void* p) {
    u32 a;
    asm("{ .reg .u64 t; cvta.to.shared.u64 t, %1; cvt.u32.u64 %0, t; }"
        : "=r"(a) : "l"(p));
    return a;
}
__device__ __forceinline__ float ex2f(float x) {
    float r;
    asm("ex2.approx.ftz.f32 %0, %1;" : "=f"(r) : "f"(x));
    return r;
}
__device__ __forceinline__ u32 bfpack(__nv_bfloat16 a, __nv_bfloat16 b) {
    __nv_bfloat162 v; v.x = a; v.y = b;
    return *(u32*)&v;
}
__device__ __forceinline__ u32 packsplit(float x, float y, u32& lo) {
    __nv_bfloat16 hx = __float2bfloat16(x), hy = __float2bfloat16(y);
    lo = bfpack(__float2bfloat16(x - __bfloat162float(hx)),
                __float2bfloat16(y - __bfloat162float(hy)));
    return bfpack(hx, hy);
}
__device__ __forceinline__ void mma_bf16(float c[4], const u32 a[4], u32 b0, u32 b1) {
    asm volatile(
        "mma.sync.aligned.m16n8k16.row.col.f32.bf16.bf16.f32 "
        "{%0,%1,%2,%3}, {%4,%5,%6,%7}, {%8,%9}, {%0,%1,%2,%3};"
        : "+f"(c[0]), "+f"(c[1]), "+f"(c[2]), "+f"(c[3])
        : "r"(a[0]), "r"(a[1]), "r"(a[2]), "r"(a[3]), "r"(b0), "r"(b1));
}
__device__ __forceinline__ void ldm4(u32* r, u32 a) {
    asm volatile("ldmatrix.sync.aligned.m8n8.x4.shared.b16 {%0,%1,%2,%3}, [%4];"
        : "=r"(r[0]), "=r"(r[1]), "=r"(r[2]), "=r"(r[3]) : "r"(a));
}

// ---------------------------------------------------------------------------
// split_w: Wt[mat][n][k] bf16 hi/lo from W[k][n] fp32.  grid 192 x 128 thr.
// ---------------------------------------------------------------------------
__global__ void split_w(const float* __restrict__ Wq,
                        const float* __restrict__ Wk,
                        const float* __restrict__ Wv) {
    const int mat = blockIdx.x >> 6;
    const int n   = blockIdx.x & 63;
    const float* W = (mat == 0) ? Wq : (mat == 1) ? Wk : Wv;
    const int k0 = threadIdx.x * 8;
    u32 h[4], l[4];
#pragma unroll
    for (int i = 0; i < 4; i++) {
        float a = W[(k0 + 2 * i) * DH + n];
        float c = W[(k0 + 2 * i + 1) * DH + n];
        h[i] = packsplit(a, c, l[i]);
    }
    const size_t idx = ((size_t)(mat * DH + n) * DIN + k0) / 2;
    *(uint4*)((u32*)g_Wh + idx) = *(uint4*)h;
    *(uint4*)((u32*)g_Wl + idx) = *(uint4*)l;
}

// ---------------------------------------------------------------------------
// qkv_mma: Y[128,64] = X[128,1024] @ W[1024,64] on HMMA with bf16 hi/lo split
// (XhWh + XlWh + XhWl). grid (128, 3) x 256 thr (8 warps, warp w = rows
// 16w..+15). X split inline during smem load; B path identical to flash K.
// Epilogue: y<2 direct split-store (Q pre-scaled); y==2 smem-bounce transpose
// into g_Vth/g_Vtl. smem 48 KB: Xh,Xl (16K each) + Wth,Wtl (8K each).
// ---------------------------------------------------------------------------
__global__ __launch_bounds__(256, 2) void qkv_mma(const float* __restrict__ X) {
    __shared__ u32 sm[12288];
    const u32 sb0 = smem_u32(sm);

    const int tid   = threadIdx.x;
    const int w     = tid >> 5;
    const int lane  = tid & 31;
    const int lane7 = lane & 7;
    const int g     = lane >> 2;
    const int t4    = lane & 3;
    const int row0  = blockIdx.x * 128;
    const int mat   = blockIdx.y;

    float o[8][4];
#pragma unroll
    for (int nb = 0; nb < 8; nb++)
#pragma unroll
        for (int e = 0; e < 4; e++) o[nb][e] = 0.f;

    for (int kc = 0; kc < 16; kc++) {
        const int k0 = kc * 64;

        // ---- Load X tile 128x64 fp32, split -> Xh/Xl (swizzled bf16) ----
#pragma unroll
        for (int i = 0; i < 4; i++) {
            const int ci = tid + 256 * i;          // chunk 0..1023
            const int r = ci >> 3, c = ci & 7;     // row, 8-elem chunk
            const float* xs = X + (size_t)(row0 + r) * DIN + k0 + c * 8;
            float4 v0 = *(const float4*)xs;
            float4 v1 = *(const float4*)(xs + 4);
            u32 h[4], l[4];
            h[0] = packsplit(v0.x, v0.y, l[0]);
            h[1] = packsplit(v0.z, v0.w, l[1]);
            h[2] = packsplit(v1.x, v1.y, l[2]);
            h[3] = packsplit(v1.z, v1.w, l[3]);
            const int off = r * 32 + ((c ^ (r & 7)) << 2);
            *(uint4*)(sm + off)        = *(uint4*)h;   // Xh @ u32 0
            *(uint4*)(sm + 4096 + off) = *(uint4*)l;   // Xl @ u32 4096
        }
        // ---- Load Wt tile 64x64 bf16 (already split) -> Wth/Wtl ----
#pragma unroll
        for (int i = 0; i < 2; i++) {
            const int ci = tid + 256 * i;          // chunk 0..511
            const int n = ci >> 3, c = ci & 7;
            const size_t gsrc = ((size_t)(mat * DH + n) * DIN + k0) / 2 + c * 4;
            uint4 vh = *(const uint4*)((const u32*)g_Wh + gsrc);
            uint4 vl = *(const uint4*)((const u32*)g_Wl + gsrc);
            const int off = n * 32 + ((c ^ (n & 7)) << 2);
            *(uint4*)(sm + 8192 + off)  = vh;      // Wth @ u32 8192
            *(uint4*)(sm + 10240 + off) = vl;      // Wtl @ u32 10240
        }
        __syncthreads();

        // ---- A-fragments (Xh/Xl) via ldmatrix ----
        u32 ah[4][4], al[4][4];
        {
            const int m  = lane >> 3, rr = lane & 7;
            const int xrow = 16 * w + rr + 8 * (m & 1);
            const u32 xbh = sb0 + (u32)(xrow * 128);
            const u32 xbl = sb0 + 16384u + (u32)(xrow * 128);
#pragma unroll
            for (int ks = 0; ks < 4; ks++) {
                const u32 off = (u32)(((2 * ks + (m >> 1)) ^ rr) << 4);
                ldm4(ah[ks], xbh + off);
                ldm4(al[ks], xbl + off);
            }
        }

        // ---- MMAs: mirror of flash QK loop ----
        const u32 bWh = sb0 + 32768u + (u32)(lane * 128);
        const u32 bWl = sb0 + 40960u + (u32)(lane * 128);
#pragma unroll
        for (int ks = 0; ks < 4; ks++) {
            const u32 c0 = (u32)(((2 * ks)     ^ lane7) << 4);
            const u32 c1 = (u32)(((2 * ks + 1) ^ lane7) << 4);
            u32 f[16];
            ldm4(f,      bWh + c0);
            ldm4(f + 4,  bWh + c1);
            ldm4(f + 8,  bWh + 4096 + c0);
            ldm4(f + 12, bWh + 4096 + c1);
#pragma unroll
            for (int nb = 0; nb < 4; nb++) {
                mma_bf16(o[nb],     ah[ks], f[nb],     f[4 + nb]);
                mma_bf16(o[nb],     al[ks], f[nb],     f[4 + nb]);
                mma_bf16(o[4 + nb], ah[ks], f[8 + nb], f[12 + nb]);
                mma_bf16(o[4 + nb], al[ks], f[8 + nb], f[12 + nb]);
            }
            u32 gf[16];
            ldm4(gf,      bWl + c0);
            ldm4(gf + 4,  bWl + c1);
            ldm4(gf + 8,  bWl + 4096 + c0);
            ldm4(gf + 12, bWl + 4096 + c1);
#pragma unroll
            for (int nb = 0; nb < 4; nb++) {
                mma_bf16(o[nb],     ah[ks], gf[nb],     gf[4 + nb]);
                mma_bf16(o[4 + nb], ah[ks], gf[8 + nb], gf[12 + nb]);
            }
        }
        __syncthreads();
    }

    // ---- Epilogue ----
    if (mat < 2) {
        const float qs = (mat == 0) ? (0.125f * 1.44269504088896340736f) : 1.f;
        u32* H = (u32*)((mat == 0) ? g_Qh : g_Kh);
        u32* L = (u32*)((mat == 0) ? g_Ql : g_Kl);
        const int ra = row0 + 16 * w + g;
        const int rb = ra + 8;
#pragma unroll
        for (int nb = 0; nb < 8; nb++) {
            u32 lo;
            u32 h = packsplit(o[nb][0] * qs, o[nb][1] * qs, lo);
            H[(size_t)ra * 32 + 4 * nb + t4] = h;
            L[(size_t)ra * 32 + 4 * nb + t4] = lo;
            h = packsplit(o[nb][2] * qs, o[nb][3] * qs, lo);
            H[(size_t)rb * 32 + 4 * nb + t4] = h;
            L[(size_t)rb * 32 + 4 * nb + t4] = lo;
        }
    } else {
        // V: bounce through smem to transpose into [b][d][s]
        float* fb = (float*)sm;              // [128][68]
        const int la = 16 * w + g, lb = la + 8;
#pragma unroll
        for (int nb = 0; nb < 8; nb++) {
            const int col = 8 * nb + 2 * t4;
            fb[la * 68 + col]     = o[nb][0];
            fb[la * 68 + col + 1] = o[nb][1];
            fb[lb * 68 + col]     = o[nb][2];
            fb[lb * 68 + col + 1] = o[nb][3];
        }
        __syncthreads();
        const int d    = tid & 63;
        const int tl0  = (tid >> 6) * 32;            // local token base
        const int b    = row0 >> 12;
        const int tok0 = (row0 & (SEQ - 1)) + tl0;   // global token base
        u32* H = (u32*)g_Vth;
        u32* L = (u32*)g_Vtl;
        const size_t base = ((size_t)b * 64 + d) * (SEQ / 2) + (tok0 >> 1);
#pragma unroll
        for (int p = 0; p < 16; p++) {
            float a = fb[(tl0 + 2 * p) * 68 + d];
            float c = fb[(tl0 + 2 * p + 1) * 68 + d];
            u32 lo;
            u32 h = packsplit(a, c, lo);
            H[base + p] = h;
            L[base + p] = lo;
        }
    }
}

// ---------------------------------------------------------------------------
// HMMA bf16-split causal flash attention — UNCHANGED from R10 (proven).
// ---------------------------------------------------------------------------
__global__ __launch_bounds__(128, 2) void flash_attn_mma(float* __restrict__ O) {
    __shared__ u32 sbuf[4][2048];   // 4 x 8 KB
    const u32 sb0 = smem_u32(sbuf);

    const int bid = blockIdx.x;
    int qt, b;
    if (bid < 148) { qt = 63 - (bid >> 2); b = bid & 3; }
    else           { qt = (bid - 148) >> 2; b = (bid - 148) & 3; }

    const int tid   = threadIdx.x;
    const int w     = tid >> 5;
    const int lane  = tid & 31;
    const int lane7 = lane & 7;
    const int g     = lane >> 2;
    const int t4    = lane & 3;
    const int i0    = qt * 64;

    if (w < 2) {
        const u32* src = (const u32*)(w == 0 ? g_Qh : g_Ql) + (size_t)(b * SEQ + i0) * 32;
        u32* dst = &sbuf[w][0];
#pragma unroll
        for (int rr = 0; rr < 2; rr++) {
            const int r = lane * 2 + rr;
            const u32* s = src + r * 32;
#pragma unroll
            for (int c = 0; c < 8; c++) {
                uint4 v = *(const uint4*)(s + c * 4);
                *(uint4*)(dst + r * 32 + ((c ^ (r & 7)) << 2)) = v;
            }
        }
    }
    __syncthreads();

    u32 qh[4][4], ql[4][4];
    {
        const int m  = lane >> 3, rr = lane & 7;
        const int qrow = 16 * w + rr + 8 * (m & 1);
        const u32 qbh = sb0 + (u32)(qrow * 128);
        const u32 qbl = sb0 + 8192u + (u32)(qrow * 128);
#pragma unroll
        for (int ks = 0; ks < 4; ks++) {
            const u32 off = (u32)(((2 * ks + (m >> 1)) ^ rr) << 4);
            ldm4(qh[ks], qbh + off);
            ldm4(ql[ks], qbl + off);
        }
    }
    __syncthreads();

    float o[8][4];
#pragma unroll
    for (int nb = 0; nb < 8; nb++)
#pragma unroll
        for (int e = 0; e < 4; e++) o[nb][e] = 0.f;
    float lacc0 = 0.f, lacc1 = 0.f;

    const u32 rowoff = (u32)(lane * 128);
    const u32 bKh = sb0 + rowoff;
    const u32 bKl = sb0 + 8192u + rowoff;
    const u32 bVh = sb0 + 16384u + rowoff;
    const u32 bVl = sb0 + 24576u + rowoff;

    for (int t = 0; t <= qt; t++) {
        const int j0 = t * 64;

        {
            const u32* src; size_t rstride;
            if (w == 0)      { src = (const u32*)g_Kh  + ((size_t)b * SEQ + j0) * 32; rstride = 32; }
            else if (w == 1) { src = (const u32*)g_Kl  + ((size_t)b * SEQ + j0) * 32; rstride = 32; }
            else if (w == 2) { src = (const u32*)g_Vth + (size_t)b * 64 * (SEQ / 2) + j0 / 2; rstride = SEQ / 2; }
            else             { src = (const u32*)g_Vtl + (size_t)b * 64 * (SEQ / 2) + j0 / 2; rstride = SEQ / 2; }
            u32* dst = &sbuf[w][0];
#pragma unroll
            for (int rr = 0; rr < 2; rr++) {
                const int r = lane * 2 + rr;
                const u32* s = src + (size_t)r * rstride;
#pragma unroll
                for (int c = 0; c < 8; c++) {
                    uint4 v = *(const uint4*)(s + c * 4);
                    *(uint4*)(dst + r * 32 + ((c ^ (r & 7)) << 2)) = v;
                }
            }
        }
        __syncthreads();

        float s[8][4];
#pragma unroll
        for (int nb = 0; nb < 8; nb++)
#pragma unroll
            for (int e = 0; e < 4; e++) s[nb][e] = 0.f;

#pragma unroll
        for (int ks = 0; ks < 4; ks++) {
            const u32 c0 = (u32)(((2 * ks)     ^ lane7) << 4);
            const u32 c1 = (u32)(((2 * ks + 1) ^ lane7) << 4);
            u32 f[16];
            ldm4(f,      bKh + c0);
            ldm4(f + 4,  bKh + c1);
            ldm4(f + 8,  bKh + 4096 + c0);
            ldm4(f + 12, bKh + 4096 + c1);
#pragma unroll
            for (int nb = 0; nb < 4; nb++) {
                mma_bf16(s[nb],     qh[ks], f[nb],     f[4 + nb]);
                mma_bf16(s[nb],     ql[ks], f[nb],     f[4 + nb]);
                mma_bf16(s[4 + nb], qh[ks], f[8 + nb], f[12 + nb]);
                mma_bf16(s[4 + nb], ql[ks], f[8 + nb], f[12 + nb]);
            }
            u32 gf[16];
            ldm4(gf,      bKl + c0);
            ldm4(gf + 4,  bKl + c1);
            ldm4(gf + 8,  bKl + 4096 + c0);
            ldm4(gf + 12, bKl + 4096 + c1);
#pragma unroll
            for (int nb = 0; nb < 4; nb++) {
                mma_bf16(s[nb],     qh[ks], gf[nb],     gf[4 + nb]);
                mma_bf16(s[4 + nb], qh[ks], gf[8 + nb], gf[12 + nb]);
            }
        }

        const bool diag = (t == qt);
        const int rowa = i0 + 16 * w + g;
        const int rowb = rowa + 8;
#pragma unroll
        for (int nb = 0; nb < 8; nb++) {
            const int colb = j0 + 8 * nb + 2 * t4;
            float p0 = ex2f(s[nb][0]); if (diag && colb     > rowa) p0 = 0.f;
            float p1 = ex2f(s[nb][1]); if (diag && colb + 1 > rowa) p1 = 0.f;
            float p2 = ex2f(s[nb][2]); if (diag && colb     > rowb) p2 = 0.f;
            float p3 = ex2f(s[nb][3]); if (diag && colb + 1 > rowb) p3 = 0.f;
            lacc0 += p0 + p1;
            lacc1 += p2 + p3;
            s[nb][0] = p0; s[nb][1] = p1; s[nb][2] = p2; s[nb][3] = p3;
        }

        u32 ph[4][4], pl[4][4];
#pragma unroll
        for (int ks = 0; ks < 4; ks++) {
            ph[ks][0] = packsplit(s[2 * ks][0],     s[2 * ks][1],     pl[ks][0]);
            ph[ks][1] = packsplit(s[2 * ks][2],     s[2 * ks][3],     pl[ks][1]);
            ph[ks][2] = packsplit(s[2 * ks + 1][0], s[2 * ks + 1][1], pl[ks][2]);
            ph[ks][3] = packsplit(s[2 * ks + 1][2], s[2 * ks + 1][3], pl[ks][3]);
        }

#pragma unroll
        for (int ks = 0; ks < 4; ks++) {
            const u32 c0 = (u32)(((2 * ks)     ^ lane7) << 4);
            const u32 c1 = (u32)(((2 * ks + 1) ^ lane7) << 4);
            u32 f[16];
            ldm4(f,      bVh + c0);
            ldm4(f + 4,  bVh + c1);
            ldm4(f + 8,  bVh + 4096 + c0);
            ldm4(f + 12, bVh + 4096 + c1);
#pragma unroll
            for (int nb = 0; nb < 4; nb++) {
                mma_bf16(o[nb],     ph[ks], f[nb],     f[4 + nb]);
                mma_bf16(o[nb],     pl[ks], f[nb],     f[4 + nb]);
                mma_bf16(o[4 + nb], ph[ks], f[8 + nb], f[12 + nb]);
                mma_bf16(o[4 + nb], pl[ks], f[8 + nb], f[12 + nb]);
            }
            u32 gf[16];
            ldm4(gf,      bVl + c0);
            ldm4(gf + 4,  bVl + c1);
            ldm4(gf + 8,  bVl + 4096 + c0);
            ldm4(gf + 12, bVl + 4096 + c1);
#pragma unroll
            for (int nb = 0; nb < 4; nb++) {
                mma_bf16(o[nb],     ph[ks], gf[nb],     gf[4 + nb]);
                mma_bf16(o[4 + nb], ph[ks], gf[8 + nb], gf[12 + nb]);
            }
        }
        __syncthreads();
    }

    lacc0 += __shfl_xor_sync(0xffffffffu, lacc0, 1);
    lacc0 += __shfl_xor_sync(0xffffffffu, lacc0, 2);
    lacc1 += __shfl_xor_sync(0xffffffffu, lacc1, 1);
    lacc1 += __shfl_xor_sync(0xffffffffu, lacc1, 2);
    const float inv0 = 1.f / lacc0;
    const float inv1 = 1.f / lacc1;

    const size_t r0g = (size_t)b * SEQ + i0 + 16 * w + g;
#pragma unroll
    for (int nb = 0; nb < 8; nb++) {
        float2 v0 = make_float2(o[nb][0] * inv0, o[nb][1] * inv0);
        float2 v1 = make_float2(o[nb][2] * inv1, o[nb][3] * inv1);
        *(float2*)(O + r0g * 64 + 8 * nb + 2 * t4)       = v0;
        *(float2*)(O + (r0g + 8) * 64 + 8 * nb + 2 * t4) = v1;
    }
}

// ---------------------------------------------------------------------------
extern "C" void kernel_launch(void* const* d_in, const int* in_sizes, int n_in,
                              void* d_out, int out_size) {
    const float* X  = (const float*)d_in[0];
    const float* Wq = (const float*)d_in[1];
    const float* Wk = (const float*)d_in[2];
    const float* Wv = (const float*)d_in[3];
    float* O = (float*)d_out;

    split_w<<<192, 128>>>(Wq, Wk, Wv);
    qkv_mma<<<dim3(128, 3), 256>>>(X);
    flash_attn_mma<<<256, 128>>>(O);
}

// round 13
// speedup vs baseline: 2.0544x; 1.0631x over previous
#include <cuda_runtime.h>
#include <cuda_bf16.h>
#include <math.h>

#define BATCH 4
#define SEQ   4096
#define DIN   1024
#define DH    64

typedef unsigned int u32;

// bf16 hi/lo split scratch
__device__ __nv_bfloat16 g_Qh[BATCH * SEQ * DH];
__device__ __nv_bfloat16 g_Ql[BATCH * SEQ * DH];
__device__ __nv_bfloat16 g_Kh[BATCH * SEQ * DH];
__device__ __nv_bfloat16 g_Kl[BATCH * SEQ * DH];
__device__ __nv_bfloat16 g_Vth[BATCH * DH * SEQ];  // transposed: [b][d][s]
__device__ __nv_bfloat16 g_Vtl[BATCH * DH * SEQ];
// W transposed+split: [mat][n][k] bf16
__device__ __nv_bfloat16 g_Wh[3 * DH * DIN];
__device__ __nv_bfloat16 g_Wl[3 * DH * DIN];
// split-KV accumulators (additive softmax partials)
__device__ float g_Oacc[BATCH * SEQ * DH];
__device__ float g_l[BATCH * SEQ];

__device__ __forceinline__ u32 smem_u32(const void* p) {
    u32 a;
    asm("{ .reg .u64 t; cvta.to.shared.u64 t, %1; cvt.u32.u64 %0, t; }"
        : "=r"(a) : "l"(p));
    return a;
}
__device__ __forceinline__ float ex2f(float x) {
    float r;
    asm("ex2.approx.ftz.f32 %0, %1;" : "=f"(r) : "f"(x));
    return r;
}
__device__ __forceinline__ u32 bfpack(__nv_bfloat16 a, __nv_bfloat16 b) {
    __nv_bfloat162 v; v.x = a; v.y = b;
    return *(u32*)&v;
}
__device__ __forceinline__ u32 packsplit(float x, float y, u32& lo) {
    __nv_bfloat16 hx = __float2bfloat16(x), hy = __float2bfloat16(y);
    lo = bfpack(__float2bfloat16(x - __bfloat162float(hx)),
                __float2bfloat16(y - __bfloat162float(hy)));
    return bfpack(hx, hy);
}
__device__ __forceinline__ void mma_bf16(float c[4], const u32 a[4], u32 b0, u32 b1) {
    asm volatile(
        "mma.sync.aligned.m16n8k16.row.col.f32.bf16.bf16.f32 "
        "{%0,%1,%2,%3}, {%4,%5,%6,%7}, {%8,%9}, {%0,%1,%2,%3};"
        : "+f"(c[0]), "+f"(c[1]), "+f"(c[2]), "+f"(c[3])
        : "r"(a[0]), "r"(a[1]), "r"(a[2]), "r"(a[3]), "r"(b0), "r"(b1));
}
__device__ __forceinline__ void ldm4(u32* r, u32 a) {
    asm volatile("ldmatrix.sync.aligned.m8n8.x4.shared.b16 {%0,%1,%2,%3}, [%4];"
        : "=r"(r[0]), "=r"(r[1]), "=r"(r[2]), "=r"(r[3]) : "r"(a));
}

// ---------------------------------------------------------------------------
// split_w: Wt[mat][n][k] bf16 hi/lo from W[k][n] fp32.  grid 192 x 128 thr.
// ---------------------------------------------------------------------------
__global__ void split_w(const float* __restrict__ Wq,
                        const float* __restrict__ Wk,
                        const float* __restrict__ Wv) {
    const int mat = blockIdx.x >> 6;
    const int n   = blockIdx.x & 63;
    const float* W = (mat == 0) ? Wq : (mat == 1) ? Wk : Wv;
    const int k0 = threadIdx.x * 8;
    u32 h[4], l[4];
#pragma unroll
    for (int i = 0; i < 4; i++) {
        float a = W[(k0 + 2 * i) * DH + n];
        float c = W[(k0 + 2 * i + 1) * DH + n];
        h[i] = packsplit(a, c, l[i]);
    }
    const size_t idx = ((size_t)(mat * DH + n) * DIN + k0) / 2;
    *(uint4*)((u32*)g_Wh + idx) = *(uint4*)h;
    *(uint4*)((u32*)g_Wl + idx) = *(uint4*)l;
}

// ---------------------------------------------------------------------------
// zero_acc: clear split-KV accumulators. 2048 x 512.
// ---------------------------------------------------------------------------
__global__ void zero_acc() {
    const int i = blockIdx.x * 512 + threadIdx.x;
    if (i < BATCH * SEQ * DH) g_Oacc[i] = 0.f;
    if (i < BATCH * SEQ)      g_l[i]    = 0.f;
}

// ---------------------------------------------------------------------------
// normalize: O = g_Oacc / g_l (row-wise). 1024 x 256, one float4 per thread.
// ---------------------------------------------------------------------------
__global__ void normalize(float* __restrict__ O) {
    const int i = blockIdx.x * 256 + threadIdx.x;   // float4 index
    float4 v = ((const float4*)g_Oacc)[i];
    const float inv = 1.f / g_l[i >> 4];
    v.x *= inv; v.y *= inv; v.z *= inv; v.w *= inv;
    ((float4*)O)[i] = v;
}

// ---------------------------------------------------------------------------
// qkv_mma (unchanged from R11 — proven).
// ---------------------------------------------------------------------------
__global__ __launch_bounds__(256, 2) void qkv_mma(const float* __restrict__ X) {
    __shared__ u32 sm[12288];
    const u32 sb0 = smem_u32(sm);

    const int tid   = threadIdx.x;
    const int w     = tid >> 5;
    const int lane  = tid & 31;
    const int lane7 = lane & 7;
    const int g     = lane >> 2;
    const int t4    = lane & 3;
    const int row0  = blockIdx.x * 128;
    const int mat   = blockIdx.y;

    float o[8][4];
#pragma unroll
    for (int nb = 0; nb < 8; nb++)
#pragma unroll
        for (int e = 0; e < 4; e++) o[nb][e] = 0.f;

    for (int kc = 0; kc < 16; kc++) {
        const int k0 = kc * 64;

#pragma unroll
        for (int i = 0; i < 4; i++) {
            const int ci = tid + 256 * i;
            const int r = ci >> 3, c = ci & 7;
            const float* xs = X + (size_t)(row0 + r) * DIN + k0 + c * 8;
            float4 v0 = *(const float4*)xs;
            float4 v1 = *(const float4*)(xs + 4);
            u32 h[4], l[4];
            h[0] = packsplit(v0.x, v0.y, l[0]);
            h[1] = packsplit(v0.z, v0.w, l[1]);
            h[2] = packsplit(v1.x, v1.y, l[2]);
            h[3] = packsplit(v1.z, v1.w, l[3]);
            const int off = r * 32 + ((c ^ (r & 7)) << 2);
            *(uint4*)(sm + off)        = *(uint4*)h;
            *(uint4*)(sm + 4096 + off) = *(uint4*)l;
        }
#pragma unroll
        for (int i = 0; i < 2; i++) {
            const int ci = tid + 256 * i;
            const int n = ci >> 3, c = ci & 7;
            const size_t gsrc = ((size_t)(mat * DH + n) * DIN + k0) / 2 + c * 4;
            uint4 vh = *(const uint4*)((const u32*)g_Wh + gsrc);
            uint4 vl = *(const uint4*)((const u32*)g_Wl + gsrc);
            const int off = n * 32 + ((c ^ (n & 7)) << 2);
            *(uint4*)(sm + 8192 + off)  = vh;
            *(uint4*)(sm + 10240 + off) = vl;
        }
        __syncthreads();

        u32 ah[4][4], al[4][4];
        {
            const int m  = lane >> 3, rr = lane & 7;
            const int xrow = 16 * w + rr + 8 * (m & 1);
            const u32 xbh = sb0 + (u32)(xrow * 128);
            const u32 xbl = sb0 + 16384u + (u32)(xrow * 128);
#pragma unroll
            for (int ks = 0; ks < 4; ks++) {
                const u32 off = (u32)(((2 * ks + (m >> 1)) ^ rr) << 4);
                ldm4(ah[ks], xbh + off);
                ldm4(al[ks], xbl + off);
            }
        }

        const u32 bWh = sb0 + 32768u + (u32)(lane * 128);
        const u32 bWl = sb0 + 40960u + (u32)(lane * 128);
#pragma unroll
        for (int ks = 0; ks < 4; ks++) {
            const u32 c0 = (u32)(((2 * ks)     ^ lane7) << 4);
            const u32 c1 = (u32)(((2 * ks + 1) ^ lane7) << 4);
            u32 f[16];
            ldm4(f,      bWh + c0);
            ldm4(f + 4,  bWh + c1);
            ldm4(f + 8,  bWh + 4096 + c0);
            ldm4(f + 12, bWh + 4096 + c1);
#pragma unroll
            for (int nb = 0; nb < 4; nb++) {
                mma_bf16(o[nb],     ah[ks], f[nb],     f[4 + nb]);
                mma_bf16(o[nb],     al[ks], f[nb],     f[4 + nb]);
                mma_bf16(o[4 + nb], ah[ks], f[8 + nb], f[12 + nb]);
                mma_bf16(o[4 + nb], al[ks], f[8 + nb], f[12 + nb]);
            }
            u32 gf[16];
            ldm4(gf,      bWl + c0);
            ldm4(gf + 4,  bWl + c1);
            ldm4(gf + 8,  bWl + 4096 + c0);
            ldm4(gf + 12, bWl + 4096 + c1);
#pragma unroll
            for (int nb = 0; nb < 4; nb++) {
                mma_bf16(o[nb],     ah[ks], gf[nb],     gf[4 + nb]);
                mma_bf16(o[4 + nb], ah[ks], gf[8 + nb], gf[12 + nb]);
            }
        }
        __syncthreads();
    }

    if (mat < 2) {
        const float qs = (mat == 0) ? (0.125f * 1.44269504088896340736f) : 1.f;
        u32* H = (u32*)((mat == 0) ? g_Qh : g_Kh);
        u32* L = (u32*)((mat == 0) ? g_Ql : g_Kl);
        const int ra = row0 + 16 * w + g;
        const int rb = ra + 8;
#pragma unroll
        for (int nb = 0; nb < 8; nb++) {
            u32 lo;
            u32 h = packsplit(o[nb][0] * qs, o[nb][1] * qs, lo);
            H[(size_t)ra * 32 + 4 * nb + t4] = h;
            L[(size_t)ra * 32 + 4 * nb + t4] = lo;
            h = packsplit(o[nb][2] * qs, o[nb][3] * qs, lo);
            H[(size_t)rb * 32 + 4 * nb + t4] = h;
            L[(size_t)rb * 32 + 4 * nb + t4] = lo;
        }
    } else {
        float* fb = (float*)sm;              // [128][68]
        const int la = 16 * w + g, lb = la + 8;
#pragma unroll
        for (int nb = 0; nb < 8; nb++) {
            const int col = 8 * nb + 2 * t4;
            fb[la * 68 + col]     = o[nb][0];
            fb[la * 68 + col + 1] = o[nb][1];
            fb[lb * 68 + col]     = o[nb][2];
            fb[lb * 68 + col + 1] = o[nb][3];
        }
        __syncthreads();
        const int d    = tid & 63;
        const int tl0  = (tid >> 6) * 32;
        const int b    = row0 >> 12;
        const int tok0 = (row0 & (SEQ - 1)) + tl0;
        u32* H = (u32*)g_Vth;
        u32* L = (u32*)g_Vtl;
        const size_t base = ((size_t)b * 64 + d) * (SEQ / 2) + (tok0 >> 1);
#pragma unroll
        for (int p = 0; p < 16; p++) {
            float a = fb[(tl0 + 2 * p) * 68 + d];
            float c = fb[(tl0 + 2 * p + 1) * 68 + d];
            u32 lo;
            u32 h = packsplit(a, c, lo);
            H[base + p] = h;
            L[base + p] = lo;
        }
    }
}

// ---------------------------------------------------------------------------
// Split-KV HMMA flash attention. Work item = (batch, q-tile, kv-chunk of up
// to 16 kv-tiles). Fixed-max softmax makes partials additive: each CTA
// atomicAdds (sum p*V) into g_Oacc and (sum p) into g_l. grid = 640, 3 CTAs/SM.
// ---------------------------------------------------------------------------
__global__ __launch_bounds__(128, 3) void flash_attn_mma() {
    __shared__ u32 sbuf[4][2048];   // 4 x 8 KB
    const u32 sb0 = smem_u32(sbuf);

    // bid -> (batch, qt, chunk): per batch 160 chunks
    const int bid = blockIdx.x;
    const int b   = bid / 160;
    const int id  = bid - b * 160;
    int qt, ch;
    if (id < 16)      { qt = id; ch = 0; }
    else if (id < 48) { int k = id - 16; qt = 16 + (k >> 1); ch = k & 1; }
    else if (id < 96) { int k = id - 48; qt = 32 + k / 3;    ch = k - (k / 3) * 3; }
    else              { int k = id - 96; qt = 48 + (k >> 2); ch = k & 3; }
    const int tA = ch * 16;
    const int tB = min(tA + 16, qt + 1);

    const int tid   = threadIdx.x;
    const int w     = tid >> 5;
    const int lane  = tid & 31;
    const int lane7 = lane & 7;
    const int g     = lane >> 2;
    const int t4    = lane & 3;
    const int i0    = qt * 64;

    // ---- Stage Q tile (hi/lo) into sbuf[0..1] ----
    if (w < 2) {
        const u32* src = (const u32*)(w == 0 ? g_Qh : g_Ql) + (size_t)(b * SEQ + i0) * 32;
        u32* dst = &sbuf[w][0];
#pragma unroll
        for (int rr = 0; rr < 2; rr++) {
            const int r = lane * 2 + rr;
            const u32* s = src + r * 32;
#pragma unroll
            for (int c = 0; c < 8; c++) {
                uint4 v = *(const uint4*)(s + c * 4);
                *(uint4*)(dst + r * 32 + ((c ^ (r & 7)) << 2)) = v;
            }
        }
    }
    __syncthreads();

    u32 qh[4][4], ql[4][4];
    {
        const int m  = lane >> 3, rr = lane & 7;
        const int qrow = 16 * w + rr + 8 * (m & 1);
        const u32 qbh = sb0 + (u32)(qrow * 128);
        const u32 qbl = sb0 + 8192u + (u32)(qrow * 128);
#pragma unroll
        for (int ks = 0; ks < 4; ks++) {
            const u32 off = (u32)(((2 * ks + (m >> 1)) ^ rr) << 4);
            ldm4(qh[ks], qbh + off);
            ldm4(ql[ks], qbl + off);
        }
    }
    __syncthreads();

    float o[8][4];
#pragma unroll
    for (int nb = 0; nb < 8; nb++)
#pragma unroll
        for (int e = 0; e < 4; e++) o[nb][e] = 0.f;
    float lacc0 = 0.f, lacc1 = 0.f;

    const u32 rowoff = (u32)(lane * 128);
    const u32 bKh = sb0 + rowoff;
    const u32 bKl = sb0 + 8192u + rowoff;
    const u32 bVh = sb0 + 16384u + rowoff;
    const u32 bVl = sb0 + 24576u + rowoff;

    for (int t = tA; t < tB; t++) {
        const int j0 = t * 64;

        // ---- Load tiles: warp w fills buffer w ----
        {
            const u32* src; size_t rstride;
            if (w == 0)      { src = (const u32*)g_Kh  + ((size_t)b * SEQ + j0) * 32; rstride = 32; }
            else if (w == 1) { src = (const u32*)g_Kl  + ((size_t)b * SEQ + j0) * 32; rstride = 32; }
            else if (w == 2) { src = (const u32*)g_Vth + (size_t)b * 64 * (SEQ / 2) + j0 / 2; rstride = SEQ / 2; }
            else             { src = (const u32*)g_Vtl + (size_t)b * 64 * (SEQ / 2) + j0 / 2; rstride = SEQ / 2; }
            u32* dst = &sbuf[w][0];
#pragma unroll
            for (int rr = 0; rr < 2; rr++) {
                const int r = lane * 2 + rr;
                const u32* s = src + (size_t)r * rstride;
#pragma unroll
                for (int c = 0; c < 8; c++) {
                    uint4 v = *(const uint4*)(s + c * 4);
                    *(uint4*)(dst + r * 32 + ((c ^ (r & 7)) << 2)) = v;
                }
            }
        }
        __syncthreads();

        // ---- S = Qh·Kh + Ql·Kh + Qh·Kl ----
        float s[8][4];
#pragma unroll
        for (int nb = 0; nb < 8; nb++)
#pragma unroll
            for (int e = 0; e < 4; e++) s[nb][e] = 0.f;

#pragma unroll
        for (int ks = 0; ks < 4; ks++) {
            const u32 c0 = (u32)(((2 * ks)     ^ lane7) << 4);
            const u32 c1 = (u32)(((2 * ks + 1) ^ lane7) << 4);
            u32 f[16];
            ldm4(f,      bKh + c0);
            ldm4(f + 4,  bKh + c1);
            ldm4(f + 8,  bKh + 4096 + c0);
            ldm4(f + 12, bKh + 4096 + c1);
#pragma unroll
            for (int nb = 0; nb < 4; nb++) {
                mma_bf16(s[nb],     qh[ks], f[nb],     f[4 + nb]);
                mma_bf16(s[nb],     ql[ks], f[nb],     f[4 + nb]);
                mma_bf16(s[4 + nb], qh[ks], f[8 + nb], f[12 + nb]);
                mma_bf16(s[4 + nb], ql[ks], f[8 + nb], f[12 + nb]);
            }
            u32 gf[16];
            ldm4(gf,      bKl + c0);
            ldm4(gf + 4,  bKl + c1);
            ldm4(gf + 8,  bKl + 4096 + c0);
            ldm4(gf + 12, bKl + 4096 + c1);
#pragma unroll
            for (int nb = 0; nb < 4; nb++) {
                mma_bf16(s[nb],     qh[ks], gf[nb],     gf[4 + nb]);
                mma_bf16(s[4 + nb], qh[ks], gf[8 + nb], gf[12 + nb]);
            }
        }

        // ---- Fixed-max softmax + causal mask on the diagonal tile ----
        const bool diag = (t == qt);
        const int rowa = i0 + 16 * w + g;
        const int rowb = rowa + 8;
#pragma unroll
        for (int nb = 0; nb < 8; nb++) {
            const int colb = j0 + 8 * nb + 2 * t4;
            float p0 = ex2f(s[nb][0]); if (diag && colb     > rowa) p0 = 0.f;
            float p1 = ex2f(s[nb][1]); if (diag && colb + 1 > rowa) p1 = 0.f;
            float p2 = ex2f(s[nb][2]); if (diag && colb     > rowb) p2 = 0.f;
            float p3 = ex2f(s[nb][3]); if (diag && colb + 1 > rowb) p3 = 0.f;
            lacc0 += p0 + p1;
            lacc1 += p2 + p3;
            s[nb][0] = p0; s[nb][1] = p1; s[nb][2] = p2; s[nb][3] = p3;
        }

        // ---- P -> bf16 hi/lo A-fragments ----
        u32 ph[4][4], pl[4][4];
#pragma unroll
        for (int ks = 0; ks < 4; ks++) {
            ph[ks][0] = packsplit(s[2 * ks][0],     s[2 * ks][1],     pl[ks][0]);
            ph[ks][1] = packsplit(s[2 * ks][2],     s[2 * ks][3],     pl[ks][1]);
            ph[ks][2] = packsplit(s[2 * ks + 1][0], s[2 * ks + 1][1], pl[ks][2]);
            ph[ks][3] = packsplit(s[2 * ks + 1][2], s[2 * ks + 1][3], pl[ks][3]);
        }

        // ---- O += Ph·Vh + Pl·Vh + Ph·Vl ----
#pragma unroll
        for (int ks = 0; ks < 4; ks++) {
            const u32 c0 = (u32)(((2 * ks)     ^ lane7) << 4);
            const u32 c1 = (u32)(((2 * ks + 1) ^ lane7) << 4);
            u32 f[16];
            ldm4(f,      bVh + c0);
            ldm4(f + 4,  bVh + c1);
            ldm4(f + 8,  bVh + 4096 + c0);
            ldm4(f + 12, bVh + 4096 + c1);
#pragma unroll
            for (int nb = 0; nb < 4; nb++) {
                mma_bf16(o[nb],     ph[ks], f[nb],     f[4 + nb]);
                mma_bf16(o[nb],     pl[ks], f[nb],     f[4 + nb]);
                mma_bf16(o[4 + nb], ph[ks], f[8 + nb], f[12 + nb]);
                mma_bf16(o[4 + nb], pl[ks], f[8 + nb], f[12 + nb]);
            }
            u32 gf[16];
            ldm4(gf,      bVl + c0);
            ldm4(gf + 4,  bVl + c1);
            ldm4(gf + 8,  bVl + 4096 + c0);
            ldm4(gf + 12, bVl + 4096 + c1);
#pragma unroll
            for (int nb = 0; nb < 4; nb++) {
                mma_bf16(o[nb],     ph[ks], gf[nb],     gf[4 + nb]);
                mma_bf16(o[4 + nb], ph[ks], gf[8 + nb], gf[12 + nb]);
            }
        }
        __syncthreads();
    }

    // ---- Accumulate partials: l via t4-group reduce + atomicAdd, O direct ----
    lacc0 += __shfl_xor_sync(0xffffffffu, lacc0, 1);
    lacc0 += __shfl_xor_sync(0xffffffffu, lacc0, 2);
    lacc1 += __shfl_xor_sync(0xffffffffu, lacc1, 1);
    lacc1 += __shfl_xor_sync(0xffffffffu, lacc1, 2);

    const int rowa = i0 + 16 * w + g;
    if (t4 == 0) {
        atomicAdd(&g_l[(size_t)b * SEQ + rowa],     lacc0);
        atomicAdd(&g_l[(size_t)b * SEQ + rowa + 8], lacc1);
    }

    float* Oa = g_Oacc + ((size_t)b * SEQ + rowa) * 64;
    float* Ob = Oa + 8 * 64;
#pragma unroll
    for (int nb = 0; nb < 8; nb++) {
        const int col = 8 * nb + 2 * t4;
        atomicAdd(Oa + col,     o[nb][0]);
        atomicAdd(Oa + col + 1, o[nb][1]);
        atomicAdd(Ob + col,     o[nb][2]);
        atomicAdd(Ob + col + 1, o[nb][3]);
    }
}

// ---------------------------------------------------------------------------
extern "C" void kernel_launch(void* const* d_in, const int* in_sizes, int n_in,
                              void* d_out, int out_size) {
    const float* X  = (const float*)d_in[0];
    const float* Wq = (const float*)d_in[1];
    const float* Wk = (const float*)d_in[2];
    const float* Wv = (const float*)d_in[3];
    float* O = (float*)d_out;

    zero_acc<<<2048, 512>>>();
    split_w<<<192, 128>>>(Wq, Wk, Wv);
    qkv_mma<<<dim3(128, 3), 256>>>(X);
    flash_attn_mma<<<640, 128>>>();
    normalize<<<1024, 256>>>(O);
}

// round 14
// speedup vs baseline: 2.1255x; 1.0346x over previous
#include <cuda_runtime.h>
#include <cuda_bf16.h>
#include <math.h>

#define BATCH 4
#define SEQ   4096
#define DIN   1024
#define DH    64

typedef unsigned int u32;

// bf16 hi/lo split scratch
__device__ __nv_bfloat16 g_Qh[BATCH * SEQ * DH];
__device__ __nv_bfloat16 g_Ql[BATCH * SEQ * DH];
__device__ __nv_bfloat16 g_Kh[BATCH * SEQ * DH];
__device__ __nv_bfloat16 g_Kl[BATCH * SEQ * DH];
__device__ __nv_bfloat16 g_Vth[BATCH * DH * SEQ];  // transposed: [b][d][s]
__device__ __nv_bfloat16 g_Vtl[BATCH * DH * SEQ];
// W transposed+split: [mat][n][k] bf16
__device__ __nv_bfloat16 g_Wh[3 * DH * DIN];
__device__ __nv_bfloat16 g_Wl[3 * DH * DIN];
// split-KV accumulators (additive softmax partials)
__device__ float g_Oacc[BATCH * SEQ * DH];
__device__ float g_l[BATCH * SEQ];

__device__ __forceinline__ u32 smem_u32(const void* p) {
    u32 a;
    asm("{ .reg .u64 t; cvta.to.shared.u64 t, %1; cvt.u32.u64 %0, t; }"
        : "=r"(a) : "l"(p));
    return a;
}
__device__ __forceinline__ float ex2f(float x) {
    float r;
    asm("ex2.approx.ftz.f32 %0, %1;" : "=f"(r) : "f"(x));
    return r;
}
__device__ __forceinline__ u32 bfpack(__nv_bfloat16 a, __nv_bfloat16 b) {
    __nv_bfloat162 v; v.x = a; v.y = b;
    return *(u32*)&v;
}
__device__ __forceinline__ u32 packsplit(float x, float y, u32& lo) {
    __nv_bfloat16 hx = __float2bfloat16(x), hy = __float2bfloat16(y);
    lo = bfpack(__float2bfloat16(x - __bfloat162float(hx)),
                __float2bfloat16(y - __bfloat162float(hy)));
    return bfpack(hx, hy);
}
__device__ __forceinline__ void mma_bf16(float c[4], const u32 a[4], u32 b0, u32 b1) {
    asm volatile(
        "mma.sync.aligned.m16n8k16.row.col.f32.bf16.bf16.f32 "
        "{%0,%1,%2,%3}, {%4,%5,%6,%7}, {%8,%9}, {%0,%1,%2,%3};"
        : "+f"(c[0]), "+f"(c[1]), "+f"(c[2]), "+f"(c[3])
        : "r"(a[0]), "r"(a[1]), "r"(a[2]), "r"(a[3]), "r"(b0), "r"(b1));
}
__device__ __forceinline__ void ldm4(u32* r, u32 a) {
    asm volatile("ldmatrix.sync.aligned.m8n8.x4.shared.b16 {%0,%1,%2,%3}, [%4];"
        : "=r"(r[0]), "=r"(r[1]), "=r"(r[2]), "=r"(r[3]) : "r"(a));
}

// ---------------------------------------------------------------------------
// split_w: Wt[mat][n][k] bf16 hi/lo from W[k][n] fp32.  grid 192 x 128 thr.
// ---------------------------------------------------------------------------
__global__ void split_w(const float* __restrict__ Wq,
                        const float* __restrict__ Wk,
                        const float* __restrict__ Wv) {
    const int mat = blockIdx.x >> 6;
    const int n   = blockIdx.x & 63;
    const float* W = (mat == 0) ? Wq : (mat == 1) ? Wk : Wv;
    const int k0 = threadIdx.x * 8;
    u32 h[4], l[4];
#pragma unroll
    for (int i = 0; i < 4; i++) {
        float a = W[(k0 + 2 * i) * DH + n];
        float c = W[(k0 + 2 * i + 1) * DH + n];
        h[i] = packsplit(a, c, l[i]);
    }
    const size_t idx = ((size_t)(mat * DH + n) * DIN + k0) / 2;
    *(uint4*)((u32*)g_Wh + idx) = *(uint4*)h;
    *(uint4*)((u32*)g_Wl + idx) = *(uint4*)l;
}

// ---------------------------------------------------------------------------
// zero_acc: clear split-KV accumulators. 2048 x 512.
// ---------------------------------------------------------------------------
__global__ void zero_acc() {
    const int i = blockIdx.x * 512 + threadIdx.x;
    if (i < BATCH * SEQ * DH) g_Oacc[i] = 0.f;
    if (i < BATCH * SEQ)      g_l[i]    = 0.f;
}

// ---------------------------------------------------------------------------
// normalize: O = g_Oacc / g_l (row-wise). 1024 x 256, one float4 per thread.
// ---------------------------------------------------------------------------
__global__ void normalize(float* __restrict__ O) {
    const int i = blockIdx.x * 256 + threadIdx.x;   // float4 index
    float4 v = ((const float4*)g_Oacc)[i];
    const float inv = 1.f / g_l[i >> 4];
    v.x *= inv; v.y *= inv; v.z *= inv; v.w *= inv;
    ((float4*)O)[i] = v;
}

// ---------------------------------------------------------------------------
// qkv_mma (unchanged — proven).
// ---------------------------------------------------------------------------
__global__ __launch_bounds__(256, 2) void qkv_mma(const float* __restrict__ X) {
    __shared__ u32 sm[12288];
    const u32 sb0 = smem_u32(sm);

    const int tid   = threadIdx.x;
    const int w     = tid >> 5;
    const int lane  = tid & 31;
    const int lane7 = lane & 7;
    const int g     = lane >> 2;
    const int t4    = lane & 3;
    const int row0  = blockIdx.x * 128;
    const int mat   = blockIdx.y;

    float o[8][4];
#pragma unroll
    for (int nb = 0; nb < 8; nb++)
#pragma unroll
        for (int e = 0; e < 4; e++) o[nb][e] = 0.f;

    for (int kc = 0; kc < 16; kc++) {
        const int k0 = kc * 64;

#pragma unroll
        for (int i = 0; i < 4; i++) {
            const int ci = tid + 256 * i;
            const int r = ci >> 3, c = ci & 7;
            const float* xs = X + (size_t)(row0 + r) * DIN + k0 + c * 8;
            float4 v0 = *(const float4*)xs;
            float4 v1 = *(const float4*)(xs + 4);
            u32 h[4], l[4];
            h[0] = packsplit(v0.x, v0.y, l[0]);
            h[1] = packsplit(v0.z, v0.w, l[1]);
            h[2] = packsplit(v1.x, v1.y, l[2]);
            h[3] = packsplit(v1.z, v1.w, l[3]);
            const int off = r * 32 + ((c ^ (r & 7)) << 2);
            *(uint4*)(sm + off)        = *(uint4*)h;
            *(uint4*)(sm + 4096 + off) = *(uint4*)l;
        }
#pragma unroll
        for (int i = 0; i < 2; i++) {
            const int ci = tid + 256 * i;
            const int n = ci >> 3, c = ci & 7;
            const size_t gsrc = ((size_t)(mat * DH + n) * DIN + k0) / 2 + c * 4;
            uint4 vh = *(const uint4*)((const u32*)g_Wh + gsrc);
            uint4 vl = *(const uint4*)((const u32*)g_Wl + gsrc);
            const int off = n * 32 + ((c ^ (n & 7)) << 2);
            *(uint4*)(sm + 8192 + off)  = vh;
            *(uint4*)(sm + 10240 + off) = vl;
        }
        __syncthreads();

        u32 ah[4][4], al[4][4];
        {
            const int m  = lane >> 3, rr = lane & 7;
            const int xrow = 16 * w + rr + 8 * (m & 1);
            const u32 xbh = sb0 + (u32)(xrow * 128);
            const u32 xbl = sb0 + 16384u + (u32)(xrow * 128);
#pragma unroll
            for (int ks = 0; ks < 4; ks++) {
                const u32 off = (u32)(((2 * ks + (m >> 1)) ^ rr) << 4);
                ldm4(ah[ks], xbh + off);
                ldm4(al[ks], xbl + off);
            }
        }

        const u32 bWh = sb0 + 32768u + (u32)(lane * 128);
        const u32 bWl = sb0 + 40960u + (u32)(lane * 128);
#pragma unroll
        for (int ks = 0; ks < 4; ks++) {
            const u32 c0 = (u32)(((2 * ks)     ^ lane7) << 4);
            const u32 c1 = (u32)(((2 * ks + 1) ^ lane7) << 4);
            u32 f[16];
            ldm4(f,      bWh + c0);
            ldm4(f + 4,  bWh + c1);
            ldm4(f + 8,  bWh + 4096 + c0);
            ldm4(f + 12, bWh + 4096 + c1);
#pragma unroll
            for (int nb = 0; nb < 4; nb++) {
                mma_bf16(o[nb],     ah[ks], f[nb],     f[4 + nb]);
                mma_bf16(o[nb],     al[ks], f[nb],     f[4 + nb]);
                mma_bf16(o[4 + nb], ah[ks], f[8 + nb], f[12 + nb]);
                mma_bf16(o[4 + nb], al[ks], f[8 + nb], f[12 + nb]);
            }
            u32 gf[16];
            ldm4(gf,      bWl + c0);
            ldm4(gf + 4,  bWl + c1);
            ldm4(gf + 8,  bWl + 4096 + c0);
            ldm4(gf + 12, bWl + 4096 + c1);
#pragma unroll
            for (int nb = 0; nb < 4; nb++) {
                mma_bf16(o[nb],     ah[ks], gf[nb],     gf[4 + nb]);
                mma_bf16(o[4 + nb], ah[ks], gf[8 + nb], gf[12 + nb]);
            }
        }
        __syncthreads();
    }

    if (mat < 2) {
        const float qs = (mat == 0) ? (0.125f * 1.44269504088896340736f) : 1.f;
        u32* H = (u32*)((mat == 0) ? g_Qh : g_Kh);
        u32* L = (u32*)((mat == 0) ? g_Ql : g_Kl);
        const int ra = row0 + 16 * w + g;
        const int rb = ra + 8;
#pragma unroll
        for (int nb = 0; nb < 8; nb++) {
            u32 lo;
            u32 h = packsplit(o[nb][0] * qs, o[nb][1] * qs, lo);
            H[(size_t)ra * 32 + 4 * nb + t4] = h;
            L[(size_t)ra * 32 + 4 * nb + t4] = lo;
            h = packsplit(o[nb][2] * qs, o[nb][3] * qs, lo);
            H[(size_t)rb * 32 + 4 * nb + t4] = h;
            L[(size_t)rb * 32 + 4 * nb + t4] = lo;
        }
    } else {
        float* fb = (float*)sm;              // [128][68]
        const int la = 16 * w + g, lb = la + 8;
#pragma unroll
        for (int nb = 0; nb < 8; nb++) {
            const int col = 8 * nb + 2 * t4;
            fb[la * 68 + col]     = o[nb][0];
            fb[la * 68 + col + 1] = o[nb][1];
            fb[lb * 68 + col]     = o[nb][2];
            fb[lb * 68 + col + 1] = o[nb][3];
        }
        __syncthreads();
        const int d    = tid & 63;
        const int tl0  = (tid >> 6) * 32;
        const int b    = row0 >> 12;
        const int tok0 = (row0 & (SEQ - 1)) + tl0;
        u32* H = (u32*)g_Vth;
        u32* L = (u32*)g_Vtl;
        const size_t base = ((size_t)b * 64 + d) * (SEQ / 2) + (tok0 >> 1);
#pragma unroll
        for (int p = 0; p < 16; p++) {
            float a = fb[(tl0 + 2 * p) * 68 + d];
            float c = fb[(tl0 + 2 * p + 1) * 68 + d];
            u32 lo;
            u32 h = packsplit(a, c, lo);
            H[base + p] = h;
            L[base + p] = lo;
        }
    }
}

// ---------------------------------------------------------------------------
// Split-KV HMMA flash attention with LPT (longest-first) chunk scheduling.
// Work item = (batch, q-tile, kv-chunk of up to 16 kv-tiles). bid map:
// batches interleaved (bid&3) and chunk ids REVERSED so the 16-tile chunks
// (high qt) launch first — greedy block scheduler then approximates LPT,
// letting early-finishing SMs backfill with the short low-qt chunks.
// ---------------------------------------------------------------------------
__global__ __launch_bounds__(128, 3) void flash_attn_mma() {
    __shared__ u32 sbuf[4][2048];   // 4 x 8 KB
    const u32 sb0 = smem_u32(sbuf);

    // bid -> (batch, qt, chunk), longest-first
    const int bid = blockIdx.x;
    const int b   = bid & 3;
    const int id  = 159 - (bid >> 2);   // descending chunk size
    int qt, ch;
    if (id < 16)      { qt = id; ch = 0; }
    else if (id < 48) { int k = id - 16; qt = 16 + (k >> 1); ch = k & 1; }
    else if (id < 96) { int k = id - 48; qt = 32 + k / 3;    ch = k - (k / 3) * 3; }
    else              { int k = id - 96; qt = 48 + (k >> 2); ch = k & 3; }
    const int tA = ch * 16;
    const int tB = min(tA + 16, qt + 1);

    const int tid   = threadIdx.x;
    const int w     = tid >> 5;
    const int lane  = tid & 31;
    const int lane7 = lane & 7;
    const int g     = lane >> 2;
    const int t4    = lane & 3;
    const int i0    = qt * 64;

    // ---- Stage Q tile (hi/lo) into sbuf[0..1] ----
    if (w < 2) {
        const u32* src = (const u32*)(w == 0 ? g_Qh : g_Ql) + (size_t)(b * SEQ + i0) * 32;
        u32* dst = &sbuf[w][0];
#pragma unroll
        for (int rr = 0; rr < 2; rr++) {
            const int r = lane * 2 + rr;
            const u32* s = src + r * 32;
#pragma unroll
            for (int c = 0; c < 8; c++) {
                uint4 v = *(const uint4*)(s + c * 4);
                *(uint4*)(dst + r * 32 + ((c ^ (r & 7)) << 2)) = v;
            }
        }
    }
    __syncthreads();

    u32 qh[4][4], ql[4][4];
    {
        const int m  = lane >> 3, rr = lane & 7;
        const int qrow = 16 * w + rr + 8 * (m & 1);
        const u32 qbh = sb0 + (u32)(qrow * 128);
        const u32 qbl = sb0 + 8192u + (u32)(qrow * 128);
#pragma unroll
        for (int ks = 0; ks < 4; ks++) {
            const u32 off = (u32)(((2 * ks + (m >> 1)) ^ rr) << 4);
            ldm4(qh[ks], qbh + off);
            ldm4(ql[ks], qbl + off);
        }
    }
    __syncthreads();

    float o[8][4];
#pragma unroll
    for (int nb = 0; nb < 8; nb++)
#pragma unroll
        for (int e = 0; e < 4; e++) o[nb][e] = 0.f;
    float lacc0 = 0.f, lacc1 = 0.f;

    const u32 rowoff = (u32)(lane * 128);
    const u32 bKh = sb0 + rowoff;
    const u32 bKl = sb0 + 8192u + rowoff;
    const u32 bVh = sb0 + 16384u + rowoff;
    const u32 bVl = sb0 + 24576u + rowoff;

    for (int t = tA; t < tB; t++) {
        const int j0 = t * 64;

        // ---- Load tiles: warp w fills buffer w ----
        {
            const u32* src; size_t rstride;
            if (w == 0)      { src = (const u32*)g_Kh  + ((size_t)b * SEQ + j0) * 32; rstride = 32; }
            else if (w == 1) { src = (const u32*)g_Kl  + ((size_t)b * SEQ + j0) * 32; rstride = 32; }
            else if (w == 2) { src = (const u32*)g_Vth + (size_t)b * 64 * (SEQ / 2) + j0 / 2; rstride = SEQ / 2; }
            else             { src = (const u32*)g_Vtl + (size_t)b * 64 * (SEQ / 2) + j0 / 2; rstride = SEQ / 2; }
            u32* dst = &sbuf[w][0];
#pragma unroll
            for (int rr = 0; rr < 2; rr++) {
                const int r = lane * 2 + rr;
                const u32* s = src + (size_t)r * rstride;
#pragma unroll
                for (int c = 0; c < 8; c++) {
                    uint4 v = *(const uint4*)(s + c * 4);
                    *(uint4*)(dst + r * 32 + ((c ^ (r & 7)) << 2)) = v;
                }
            }
        }
        __syncthreads();

        // ---- S = Qh·Kh + Ql·Kh + Qh·Kl ----
        float s[8][4];
#pragma unroll
        for (int nb = 0; nb < 8; nb++)
#pragma unroll
            for (int e = 0; e < 4; e++) s[nb][e] = 0.f;

#pragma unroll
        for (int ks = 0; ks < 4; ks++) {
            const u32 c0 = (u32)(((2 * ks)     ^ lane7) << 4);
            const u32 c1 = (u32)(((2 * ks + 1) ^ lane7) << 4);
            u32 f[16];
            ldm4(f,      bKh + c0);
            ldm4(f + 4,  bKh + c1);
            ldm4(f + 8,  bKh + 4096 + c0);
            ldm4(f + 12, bKh + 4096 + c1);
#pragma unroll
            for (int nb = 0; nb < 4; nb++) {
                mma_bf16(s[nb],     qh[ks], f[nb],     f[4 + nb]);
                mma_bf16(s[nb],     ql[ks], f[nb],     f[4 + nb]);
                mma_bf16(s[4 + nb], qh[ks], f[8 + nb], f[12 + nb]);
                mma_bf16(s[4 + nb], ql[ks], f[8 + nb], f[12 + nb]);
            }
            u32 gf[16];
            ldm4(gf,      bKl + c0);
            ldm4(gf + 4,  bKl + c1);
            ldm4(gf + 8,  bKl + 4096 + c0);
            ldm4(gf + 12, bKl + 4096 + c1);
#pragma unroll
            for (int nb = 0; nb < 4; nb++) {
                mma_bf16(s[nb],     qh[ks], gf[nb],     gf[4 + nb]);
                mma_bf16(s[4 + nb], qh[ks], gf[8 + nb], gf[12 + nb]);
            }
        }

        // ---- Fixed-max softmax + causal mask on the diagonal tile ----
        const bool diag = (t == qt);
        const int rowa = i0 + 16 * w + g;
        const int rowb = rowa + 8;
#pragma unroll
        for (int nb = 0; nb < 8; nb++) {
            const int colb = j0 + 8 * nb + 2 * t4;
            float p0 = ex2f(s[nb][0]); if (diag && colb     > rowa) p0 = 0.f;
            float p1 = ex2f(s[nb][1]); if (diag && colb + 1 > rowa) p1 = 0.f;
            float p2 = ex2f(s[nb][2]); if (diag && colb     > rowb) p2 = 0.f;
            float p3 = ex2f(s[nb][3]); if (diag && colb + 1 > rowb) p3 = 0.f;
            lacc0 += p0 + p1;
            lacc1 += p2 + p3;
            s[nb][0] = p0; s[nb][1] = p1; s[nb][2] = p2; s[nb][3] = p3;
        }

        // ---- P -> bf16 hi/lo A-fragments ----
        u32 ph[4][4], pl[4][4];
#pragma unroll
        for (int ks = 0; ks < 4; ks++) {
            ph[ks][0] = packsplit(s[2 * ks][0],     s[2 * ks][1],     pl[ks][0]);
            ph[ks][1] = packsplit(s[2 * ks][2],     s[2 * ks][3],     pl[ks][1]);
            ph[ks][2] = packsplit(s[2 * ks + 1][0], s[2 * ks + 1][1], pl[ks][2]);
            ph[ks][3] = packsplit(s[2 * ks + 1][2], s[2 * ks + 1][3], pl[ks][3]);
        }

        // ---- O += Ph·Vh + Pl·Vh + Ph·Vl ----
#pragma unroll
        for (int ks = 0; ks < 4; ks++) {
            const u32 c0 = (u32)(((2 * ks)     ^ lane7) << 4);
            const u32 c1 = (u32)(((2 * ks + 1) ^ lane7) << 4);
            u32 f[16];
            ldm4(f,      bVh + c0);
            ldm4(f + 4,  bVh + c1);
            ldm4(f + 8,  bVh + 4096 + c0);
            ldm4(f + 12, bVh + 4096 + c1);
#pragma unroll
            for (int nb = 0; nb < 4; nb++) {
                mma_bf16(o[nb],     ph[ks], f[nb],     f[4 + nb]);
                mma_bf16(o[nb],     pl[ks], f[nb],     f[4 + nb]);
                mma_bf16(o[4 + nb], ph[ks], f[8 + nb], f[12 + nb]);
                mma_bf16(o[4 + nb], pl[ks], f[8 + nb], f[12 + nb]);
            }
            u32 gf[16];
            ldm4(gf,      bVl + c0);
            ldm4(gf + 4,  bVl + c1);
            ldm4(gf + 8,  bVl + 4096 + c0);
            ldm4(gf + 12, bVl + 4096 + c1);
#pragma unroll
            for (int nb = 0; nb < 4; nb++) {
                mma_bf16(o[nb],     ph[ks], gf[nb],     gf[4 + nb]);
                mma_bf16(o[4 + nb], ph[ks], gf[8 + nb], gf[12 + nb]);
            }
        }
        __syncthreads();
    }

    // ---- Accumulate partials: l via t4-group reduce + atomicAdd, O direct ----
    lacc0 += __shfl_xor_sync(0xffffffffu, lacc0, 1);
    lacc0 += __shfl_xor_sync(0xffffffffu, lacc0, 2);
    lacc1 += __shfl_xor_sync(0xffffffffu, lacc1, 1);
    lacc1 += __shfl_xor_sync(0xffffffffu, lacc1, 2);

    const int rowa = i0 + 16 * w + g;
    if (t4 == 0) {
        atomicAdd(&g_l[(size_t)b * SEQ + rowa],     lacc0);
        atomicAdd(&g_l[(size_t)b * SEQ + rowa + 8], lacc1);
    }

    float* Oa = g_Oacc + ((size_t)b * SEQ + rowa) * 64;
    float* Ob = Oa + 8 * 64;
#pragma unroll
    for (int nb = 0; nb < 8; nb++) {
        const int col = 8 * nb + 2 * t4;
        atomicAdd(Oa + col,     o[nb][0]);
        atomicAdd(Oa + col + 1, o[nb][1]);
        atomicAdd(Ob + col,     o[nb][2]);
        atomicAdd(Ob + col + 1, o[nb][3]);
    }
}

// ---------------------------------------------------------------------------
extern "C" void kernel_launch(void* const* d_in, const int* in_sizes, int n_in,
                              void* d_out, int out_size) {
    const float* X  = (const float*)d_in[0];
    const float* Wq = (const float*)d_in[1];
    const float* Wk = (const float*)d_in[2];
    const float* Wv = (const float*)d_in[3];
    float* O = (float*)d_out;

    zero_acc<<<2048, 512>>>();
    split_w<<<192, 128>>>(Wq, Wk, Wv);
    qkv_mma<<<dim3(128, 3), 256>>>(X);
    flash_attn_mma<<<640, 128>>>();
    normalize<<<1024, 256>>>(O);
}

// round 16
// speedup vs baseline: 2.3372x; 1.0996x over previous
#include <cuda_runtime.h>
#include <cuda_bf16.h>
#include <math.h>

#define BATCH 4
#define SEQ   4096
#define DIN   1024
#define DH    64

typedef unsigned int u32;

// bf16 hi/lo split scratch
__device__ __nv_bfloat16 g_Qh[BATCH * SEQ * DH];
__device__ __nv_bfloat16 g_Ql[BATCH * SEQ * DH];
__device__ __nv_bfloat16 g_Kh[BATCH * SEQ * DH];
__device__ __nv_bfloat16 g_Kl[BATCH * SEQ * DH];
__device__ __nv_bfloat16 g_Vth[BATCH * DH * SEQ];  // transposed: [b][d][s]
__device__ __nv_bfloat16 g_Vtl[BATCH * DH * SEQ];
// W transposed+split: [mat][n][k] bf16
__device__ __nv_bfloat16 g_Wh[3 * DH * DIN];
__device__ __nv_bfloat16 g_Wl[3 * DH * DIN];
// split-KV accumulators (additive softmax partials)
__device__ float g_Oacc[BATCH * SEQ * DH];
__device__ float g_l[BATCH * SEQ];

__device__ __forceinline__ u32 smem_u32(const void* p) {
    u32 a;
    asm("{ .reg .u64 t; cvta.to.shared.u64 t, %1; cvt.u32.u64 %0, t; }"
        : "=r"(a) : "l"(p));
    return a;
}
__device__ __forceinline__ float ex2f(float x) {
    float r;
    asm("ex2.approx.ftz.f32 %0, %1;" : "=f"(r) : "f"(x));
    return r;
}
__device__ __forceinline__ u32 bfpack(__nv_bfloat16 a, __nv_bfloat16 b) {
    __nv_bfloat162 v; v.x = a; v.y = b;
    return *(u32*)&v;
}
__device__ __forceinline__ u32 packsplit(float x, float y, u32& lo) {
    __nv_bfloat16 hx = __float2bfloat16(x), hy = __float2bfloat16(y);
    lo = bfpack(__float2bfloat16(x - __bfloat162float(hx)),
                __float2bfloat16(y - __bfloat162float(hy)));
    return bfpack(hx, hy);
}
__device__ __forceinline__ void mma_bf16(float c[4], const u32 a[4], u32 b0, u32 b1) {
    asm volatile(
        "mma.sync.aligned.m16n8k16.row.col.f32.bf16.bf16.f32 "
        "{%0,%1,%2,%3}, {%4,%5,%6,%7}, {%8,%9}, {%0,%1,%2,%3};"
        : "+f"(c[0]), "+f"(c[1]), "+f"(c[2]), "+f"(c[3])
        : "r"(a[0]), "r"(a[1]), "r"(a[2]), "r"(a[3]), "r"(b0), "r"(b1));
}
__device__ __forceinline__ void ldm4(u32* r, u32 a) {
    asm volatile("ldmatrix.sync.aligned.m8n8.x4.shared.b16 {%0,%1,%2,%3}, [%4];"
        : "=r"(r[0]), "=r"(r[1]), "=r"(r[2]), "=r"(r[3]) : "r"(a));
}
// L1-enabled async copy (16 B)
__device__ __forceinline__ void cp16(u32 s, const void* g) {
    asm volatile("cp.async.ca.shared.global [%0], [%1], 16;" :: "r"(s), "l"(g) : "memory");
}
#define CP_COMMIT() asm volatile("cp.async.commit_group;" ::: "memory")
#define CP_WAIT(n)  asm volatile("cp.async.wait_group %0;" :: "n"(n) : "memory")

// ---------------------------------------------------------------------------
// split_w: Wt[mat][n][k] bf16 hi/lo from W[k][n] fp32.  grid 192 x 128 thr.
// ---------------------------------------------------------------------------
__global__ void split_w(const float* __restrict__ Wq,
                        const float* __restrict__ Wk,
                        const float* __restrict__ Wv) {
    const int mat = blockIdx.x >> 6;
    const int n   = blockIdx.x & 63;
    const float* W = (mat == 0) ? Wq : (mat == 1) ? Wk : Wv;
    const int k0 = threadIdx.x * 8;
    u32 h[4], l[4];
#pragma unroll
    for (int i = 0; i < 4; i++) {
        float a = W[(k0 + 2 * i) * DH + n];
        float c = W[(k0 + 2 * i + 1) * DH + n];
        h[i] = packsplit(a, c, l[i]);
    }
    const size_t idx = ((size_t)(mat * DH + n) * DIN + k0) / 2;
    *(uint4*)((u32*)g_Wh + idx) = *(uint4*)h;
    *(uint4*)((u32*)g_Wl + idx) = *(uint4*)l;
}

// ---------------------------------------------------------------------------
// zero_acc: clear split-KV accumulators. 2048 x 512.
// ---------------------------------------------------------------------------
__global__ void zero_acc() {
    const int i = blockIdx.x * 512 + threadIdx.x;
    if (i < BATCH * SEQ * DH) g_Oacc[i] = 0.f;
    if (i < BATCH * SEQ)      g_l[i]    = 0.f;
}

// ---------------------------------------------------------------------------
// normalize: O = g_Oacc / g_l (row-wise). 1024 x 256, one float4 per thread.
// ---------------------------------------------------------------------------
__global__ void normalize(float* __restrict__ O) {
    const int i = blockIdx.x * 256 + threadIdx.x;   // float4 index
    float4 v = ((const float4*)g_Oacc)[i];
    const float inv = 1.f / g_l[i >> 4];
    v.x *= inv; v.y *= inv; v.z *= inv; v.w *= inv;
    ((float4*)O)[i] = v;
}

// ---------------------------------------------------------------------------
// qkv_mma (unchanged — proven).
// ---------------------------------------------------------------------------
__global__ __launch_bounds__(256, 2) void qkv_mma(const float* __restrict__ X) {
    __shared__ u32 sm[12288];
    const u32 sb0 = smem_u32(sm);

    const int tid   = threadIdx.x;
    const int w     = tid >> 5;
    const int lane  = tid & 31;
    const int lane7 = lane & 7;
    const int g     = lane >> 2;
    const int t4    = lane & 3;
    const int row0  = blockIdx.x * 128;
    const int mat   = blockIdx.y;

    float o[8][4];
#pragma unroll
    for (int nb = 0; nb < 8; nb++)
#pragma unroll
        for (int e = 0; e < 4; e++) o[nb][e] = 0.f;

    for (int kc = 0; kc < 16; kc++) {
        const int k0 = kc * 64;

#pragma unroll
        for (int i = 0; i < 4; i++) {
            const int ci = tid + 256 * i;
            const int r = ci >> 3, c = ci & 7;
            const float* xs = X + (size_t)(row0 + r) * DIN + k0 + c * 8;
            float4 v0 = *(const float4*)xs;
            float4 v1 = *(const float4*)(xs + 4);
            u32 h[4], l[4];
            h[0] = packsplit(v0.x, v0.y, l[0]);
            h[1] = packsplit(v0.z, v0.w, l[1]);
            h[2] = packsplit(v1.x, v1.y, l[2]);
            h[3] = packsplit(v1.z, v1.w, l[3]);
            const int off = r * 32 + ((c ^ (r & 7)) << 2);
            *(uint4*)(sm + off)        = *(uint4*)h;
            *(uint4*)(sm + 4096 + off) = *(uint4*)l;
        }
#pragma unroll
        for (int i = 0; i < 2; i++) {
            const int ci = tid + 256 * i;
            const int n = ci >> 3, c = ci & 7;
            const size_t gsrc = ((size_t)(mat * DH + n) * DIN + k0) / 2 + c * 4;
            uint4 vh = *(const uint4*)((const u32*)g_Wh + gsrc);
            uint4 vl = *(const uint4*)((const u32*)g_Wl + gsrc);
            const int off = n * 32 + ((c ^ (n & 7)) << 2);
            *(uint4*)(sm + 8192 + off)  = vh;
            *(uint4*)(sm + 10240 + off) = vl;
        }
        __syncthreads();

        u32 ah[4][4], al[4][4];
        {
            const int m  = lane >> 3, rr = lane & 7;
            const int xrow = 16 * w + rr + 8 * (m & 1);
            const u32 xbh = sb0 + (u32)(xrow * 128);
            const u32 xbl = sb0 + 16384u + (u32)(xrow * 128);
#pragma unroll
            for (int ks = 0; ks < 4; ks++) {
                const u32 off = (u32)(((2 * ks + (m >> 1)) ^ rr) << 4);
                ldm4(ah[ks], xbh + off);
                ldm4(al[ks], xbl + off);
            }
        }

        const u32 bWh = sb0 + 32768u + (u32)(lane * 128);
        const u32 bWl = sb0 + 40960u + (u32)(lane * 128);
#pragma unroll
        for (int ks = 0; ks < 4; ks++) {
            const u32 c0 = (u32)(((2 * ks)     ^ lane7) << 4);
            const u32 c1 = (u32)(((2 * ks + 1) ^ lane7) << 4);
            u32 f[16];
            ldm4(f,      bWh + c0);
            ldm4(f + 4,  bWh + c1);
            ldm4(f + 8,  bWh + 4096 + c0);
            ldm4(f + 12, bWh + 4096 + c1);
#pragma unroll
            for (int nb = 0; nb < 4; nb++) {
                mma_bf16(o[nb],     ah[ks], f[nb],     f[4 + nb]);
                mma_bf16(o[nb],     al[ks], f[nb],     f[4 + nb]);
                mma_bf16(o[4 + nb], ah[ks], f[8 + nb], f[12 + nb]);
                mma_bf16(o[4 + nb], al[ks], f[8 + nb], f[12 + nb]);
            }
            u32 gf[16];
            ldm4(gf,      bWl + c0);
            ldm4(gf + 4,  bWl + c1);
            ldm4(gf + 8,  bWl + 4096 + c0);
            ldm4(gf + 12, bWl + 4096 + c1);
#pragma unroll
            for (int nb = 0; nb < 4; nb++) {
                mma_bf16(o[nb],     ah[ks], gf[nb],     gf[4 + nb]);
                mma_bf16(o[4 + nb], ah[ks], gf[8 + nb], gf[12 + nb]);
            }
        }
        __syncthreads();
    }

    if (mat < 2) {
        const float qs = (mat == 0) ? (0.125f * 1.44269504088896340736f) : 1.f;
        u32* H = (u32*)((mat == 0) ? g_Qh : g_Kh);
        u32* L = (u32*)((mat == 0) ? g_Ql : g_Kl);
        const int ra = row0 + 16 * w + g;
        const int rb = ra + 8;
#pragma unroll
        for (int nb = 0; nb < 8; nb++) {
            u32 lo;
            u32 h = packsplit(o[nb][0] * qs, o[nb][1] * qs, lo);
            H[(size_t)ra * 32 + 4 * nb + t4] = h;
            L[(size_t)ra * 32 + 4 * nb + t4] = lo;
            h = packsplit(o[nb][2] * qs, o[nb][3] * qs, lo);
            H[(size_t)rb * 32 + 4 * nb + t4] = h;
            L[(size_t)rb * 32 + 4 * nb + t4] = lo;
        }
    } else {
        float* fb = (float*)sm;              // [128][68]
        const int la = 16 * w + g, lb = la + 8;
#pragma unroll
        for (int nb = 0; nb < 8; nb++) {
            const int col = 8 * nb + 2 * t4;
            fb[la * 68 + col]     = o[nb][0];
            fb[la * 68 + col + 1] = o[nb][1];
            fb[lb * 68 + col]     = o[nb][2];
            fb[lb * 68 + col + 1] = o[nb][3];
        }
        __syncthreads();
        const int d    = tid & 63;
        const int tl0  = (tid >> 6) * 32;
        const int b    = row0 >> 12;
        const int tok0 = (row0 & (SEQ - 1)) + tl0;
        u32* H = (u32*)g_Vth;
        u32* L = (u32*)g_Vtl;
        const size_t base = ((size_t)b * 64 + d) * (SEQ / 2) + (tok0 >> 1);
#pragma unroll
        for (int p = 0; p < 16; p++) {
            float a = fb[(tl0 + 2 * p) * 68 + d];
            float c = fb[(tl0 + 2 * p + 1) * 68 + d];
            u32 lo;
            u32 h = packsplit(a, c, lo);
            H[base + p] = h;
            L[base + p] = lo;
        }
    }
}

// ---------------------------------------------------------------------------
// cp.async prefetch of one kv tile into buffer set (t&1)*4 + w.
// Buffers: 0=Kh 1=Kl 2=Vth 3=Vtl (+4 for odd t). Rows = 32 u32 (128 B),
// 16B chunk c of row r stored at chunk c ^ (r & 7). One commit group/warp.
// ---------------------------------------------------------------------------
__device__ __forceinline__ void prefetch_tile(int t, int b, int w, int lane, u32 sb0) {
    const int j0 = t * 64;
    const u32* src; size_t rstride;
    if (w == 0)      { src = (const u32*)g_Kh  + ((size_t)b * SEQ + j0) * 32; rstride = 32; }
    else if (w == 1) { src = (const u32*)g_Kl  + ((size_t)b * SEQ + j0) * 32; rstride = 32; }
    else if (w == 2) { src = (const u32*)g_Vth + (size_t)b * 64 * (SEQ / 2) + j0 / 2; rstride = SEQ / 2; }
    else             { src = (const u32*)g_Vtl + (size_t)b * 64 * (SEQ / 2) + j0 / 2; rstride = SEQ / 2; }
    const u32 dst = sb0 + (u32)(((t & 1) * 4 + w) * 8192);
#pragma unroll
    for (int rr = 0; rr < 2; rr++) {
        const int r = lane * 2 + rr;
        const u32* s = src + (size_t)r * rstride;
        const u32 da = dst + (u32)(r * 128);
        const int sw = r & 7;
#pragma unroll
        for (int c = 0; c < 8; c++)
            cp16(da + (u32)((c ^ sw) << 4), s + c * 4);
    }
    CP_COMMIT();
}

// ---------------------------------------------------------------------------
// Split-KV HMMA flash attention, LPT schedule, double-buffered cp.async.ca
// K/V prefetch. 640 CTAs x 128 thr, 3 CTAs/SM (64 KB dynamic smem each).
// tA is always even, so buffer set = t&1; Q stages in set 1 (buffers 4,5)
// and is fully extracted before iteration tA issues the set-1 prefetch.
// ---------------------------------------------------------------------------
__global__ __launch_bounds__(128, 3) void flash_attn_mma() {
    extern __shared__ __align__(16) u32 sdyn[];
    const u32 sb0 = smem_u32(sdyn);

    // bid -> (batch, qt, chunk), longest-first (LPT)
    const int bid = blockIdx.x;
    const int b   = bid & 3;
    const int id  = 159 - (bid >> 2);
    int qt, ch;
    if (id < 16)      { qt = id; ch = 0; }
    else if (id < 48) { int k = id - 16; qt = 16 + (k >> 1); ch = k & 1; }
    else if (id < 96) { int k = id - 48; qt = 32 + k / 3;    ch = k - (k / 3) * 3; }
    else              { int k = id - 96; qt = 48 + (k >> 2); ch = k & 3; }
    const int tA = ch * 16;                 // always even
    const int tB = min(tA + 16, qt + 1);

    const int tid   = threadIdx.x;
    const int w     = tid >> 5;
    const int lane  = tid & 31;
    const int lane7 = lane & 7;
    const int g     = lane >> 2;
    const int t4    = lane & 3;
    const int i0    = qt * 64;

    // ---- Prefetch first kv tile (set 0) ----
    prefetch_tile(tA, b, w, lane, sb0);

    // ---- Stage Q (hi/lo) into buffers 4,5 (set 1, free until tile tA+1) ----
    if (w < 2) {
        const u32* src = (const u32*)(w == 0 ? g_Qh : g_Ql) + (size_t)(b * SEQ + i0) * 32;
        u32* dst = sdyn + (4 + w) * 2048;
#pragma unroll
        for (int rr = 0; rr < 2; rr++) {
            const int r = lane * 2 + rr;
            const u32* s = src + r * 32;
#pragma unroll
            for (int c = 0; c < 8; c++)
                *(uint4*)(dst + r * 32 + ((c ^ (r & 7)) << 2)) = *(const uint4*)(s + c * 4);
        }
    }
    __syncthreads();

    // ---- Extract Q A-fragments via ldmatrix ----
    u32 qh[4][4], ql[4][4];
    {
        const int m  = lane >> 3, rr = lane & 7;
        const int qrow = 16 * w + rr + 8 * (m & 1);
        const u32 qbh = sb0 + 4u * 8192 + (u32)(qrow * 128);
        const u32 qbl = sb0 + 5u * 8192 + (u32)(qrow * 128);
#pragma unroll
        for (int ks = 0; ks < 4; ks++) {
            const u32 off = (u32)(((2 * ks + (m >> 1)) ^ rr) << 4);
            ldm4(qh[ks], qbh + off);
            ldm4(ql[ks], qbl + off);
        }
    }
    __syncthreads();   // Q fully extracted before set 1 is overwritten

    float o[8][4];
#pragma unroll
    for (int nb = 0; nb < 8; nb++)
#pragma unroll
        for (int e = 0; e < 4; e++) o[nb][e] = 0.f;
    float lacc0 = 0.f, lacc1 = 0.f;

    const u32 rowoff = (u32)(lane * 128);

    for (int t = tA; t < tB; t++) {
        const int j0 = t * 64;

        // Prefetch next tile into the other set, then wait for THIS tile.
        if (t + 1 < tB) {
            prefetch_tile(t + 1, b, w, lane, sb0);
            CP_WAIT(1);    // tile t's group complete; t+1 still in flight
        } else {
            CP_WAIT(0);
        }
        __syncthreads();

        const u32 base = sb0 + (u32)((t & 1) * 4 * 8192);
        const u32 bKh = base + rowoff;
        const u32 bKl = base + 8192u + rowoff;
        const u32 bVh = base + 16384u + rowoff;
        const u32 bVl = base + 24576u + rowoff;

        // ---- S = Qh·Kh + Ql·Kh + Qh·Kl ----
        float s[8][4];
#pragma unroll
        for (int nb = 0; nb < 8; nb++)
#pragma unroll
            for (int e = 0; e < 4; e++) s[nb][e] = 0.f;

#pragma unroll
        for (int ks = 0; ks < 4; ks++) {
            const u32 c0 = (u32)(((2 * ks)     ^ lane7) << 4);
            const u32 c1 = (u32)(((2 * ks + 1) ^ lane7) << 4);
            u32 f[16];
            ldm4(f,      bKh + c0);
            ldm4(f + 4,  bKh + c1);
            ldm4(f + 8,  bKh + 4096 + c0);
            ldm4(f + 12, bKh + 4096 + c1);
#pragma unroll
            for (int nb = 0; nb < 4; nb++) {
                mma_bf16(s[nb],     qh[ks], f[nb],     f[4 + nb]);
                mma_bf16(s[nb],     ql[ks], f[nb],     f[4 + nb]);
                mma_bf16(s[4 + nb], qh[ks], f[8 + nb], f[12 + nb]);
                mma_bf16(s[4 + nb], ql[ks], f[8 + nb], f[12 + nb]);
            }
            u32 gf[16];
            ldm4(gf,      bKl + c0);
            ldm4(gf + 4,  bKl + c1);
            ldm4(gf + 8,  bKl + 4096 + c0);
            ldm4(gf + 12, bKl + 4096 + c1);
#pragma unroll
            for (int nb = 0; nb < 4; nb++) {
                mma_bf16(s[nb],     qh[ks], gf[nb],     gf[4 + nb]);
                mma_bf16(s[4 + nb], qh[ks], gf[8 + nb], gf[12 + nb]);
            }
        }

        // ---- Fixed-max softmax + causal mask on the diagonal tile ----
        const bool diag = (t == qt);
        const int rowa = i0 + 16 * w + g;
        const int rowb = rowa + 8;
#pragma unroll
        for (int nb = 0; nb < 8; nb++) {
            const int colb = j0 + 8 * nb + 2 * t4;
            float p0 = ex2f(s[nb][0]); if (diag && colb     > rowa) p0 = 0.f;
            float p1 = ex2f(s[nb][1]); if (diag && colb + 1 > rowa) p1 = 0.f;
            float p2 = ex2f(s[nb][2]); if (diag && colb     > rowb) p2 = 0.f;
            float p3 = ex2f(s[nb][3]); if (diag && colb + 1 > rowb) p3 = 0.f;
            lacc0 += p0 + p1;
            lacc1 += p2 + p3;
            s[nb][0] = p0; s[nb][1] = p1; s[nb][2] = p2; s[nb][3] = p3;
        }

        // ---- P -> bf16 hi/lo A-fragments ----
        u32 ph[4][4], pl[4][4];
#pragma unroll
        for (int ks = 0; ks < 4; ks++) {
            ph[ks][0] = packsplit(s[2 * ks][0],     s[2 * ks][1],     pl[ks][0]);
            ph[ks][1] = packsplit(s[2 * ks][2],     s[2 * ks][3],     pl[ks][1]);
            ph[ks][2] = packsplit(s[2 * ks + 1][0], s[2 * ks + 1][1], pl[ks][2]);
            ph[ks][3] = packsplit(s[2 * ks + 1][2], s[2 * ks + 1][3], pl[ks][3]);
        }

        // ---- O += Ph·Vh + Pl·Vh + Ph·Vl ----
#pragma unroll
        for (int ks = 0; ks < 4; ks++) {
            const u32 c0 = (u32)(((2 * ks)     ^ lane7) << 4);
            const u32 c1 = (u32)(((2 * ks + 1) ^ lane7) << 4);
            u32 f[16];
            ldm4(f,      bVh + c0);
            ldm4(f + 4,  bVh + c1);
            ldm4(f + 8,  bVh + 4096 + c0);
            ldm4(f + 12, bVh + 4096 + c1);
#pragma unroll
            for (int nb = 0; nb < 4; nb++) {
                mma_bf16(o[nb],     ph[ks], f[nb],     f[4 + nb]);
                mma_bf16(o[nb],     pl[ks], f[nb],     f[4 + nb]);
                mma_bf16(o[4 + nb], ph[ks], f[8 + nb], f[12 + nb]);
                mma_bf16(o[4 + nb], pl[ks], f[8 + nb], f[12 + nb]);
            }
            u32 gf[16];
            ldm4(gf,      bVl + c0);
            ldm4(gf + 4,  bVl + c1);
            ldm4(gf + 8,  bVl + 4096 + c0);
            ldm4(gf + 12, bVl + 4096 + c1);
#pragma unroll
            for (int nb = 0; nb < 4; nb++) {
                mma_bf16(o[nb],     ph[ks], gf[nb],     gf[4 + nb]);
                mma_bf16(o[4 + nb], ph[ks], gf[8 + nb], gf[12 + nb]);
            }
        }
        __syncthreads();   // all warps done reading this set before it is
                           // overwritten by the prefetch two iterations on
    }

    // ---- Accumulate partials: l via t4-group reduce + atomicAdd, O direct ----
    lacc0 += __shfl_xor_sync(0xffffffffu, lacc0, 1);
    lacc0 += __shfl_xor_sync(0xffffffffu, lacc0, 2);
    lacc1 += __shfl_xor_sync(0xffffffffu, lacc1, 1);
    lacc1 += __shfl_xor_sync(0xffffffffu, lacc1, 2);

    const int rowa = i0 + 16 * w + g;
    if (t4 == 0) {
        atomicAdd(&g_l[(size_t)b * SEQ + rowa],     lacc0);
        atomicAdd(&g_l[(size_t)b * SEQ + rowa + 8], lacc1);
    }

    float* Oa = g_Oacc + ((size_t)b * SEQ + rowa) * 64;
    float* Ob = Oa + 8 * 64;
#pragma unroll
    for (int nb = 0; nb < 8; nb++) {
        const int col = 8 * nb + 2 * t4;
        atomicAdd(Oa + col,     o[nb][0]);
        atomicAdd(Oa + col + 1, o[nb][1]);
        atomicAdd(Ob + col,     o[nb][2]);
        atomicAdd(Ob + col + 1, o[nb][3]);
    }
}

// ---------------------------------------------------------------------------
extern "C" void kernel_launch(void* const* d_in, const int* in_sizes, int n_in,
                              void* d_out, int out_size) {
    const float* X  = (const float*)d_in[0];
    const float* Wq = (const float*)d_in[1];
    const float* Wk = (const float*)d_in[2];
    const float* Wv = (const float*)d_in[3];
    float* O = (float*)d_out;

    static int attr_set = 0;
    if (!attr_set) {
        cudaFuncSetAttribute(flash_attn_mma,
                             cudaFuncAttributeMaxDynamicSharedMemorySize, 65536);
        attr_set = 1;
    }

    zero_acc<<<2048, 512>>>();
    split_w<<<192, 128>>>(Wq, Wk, Wv);
    qkv_mma<<<dim3(128, 3), 256>>>(X);
    flash_attn_mma<<<640, 128, 65536>>>();
    normalize<<<1024, 256>>>(O);
}

// round 17
// speedup vs baseline: 2.4190x; 1.0350x over previous
#include <cuda_runtime.h>
#include <cuda_bf16.h>
#include <math.h>

#define BATCH 4
#define SEQ   4096
#define DIN   1024
#define DH    64

typedef unsigned int u32;

// bf16 hi/lo split scratch
__device__ __nv_bfloat16 g_Qh[BATCH * SEQ * DH];
__device__ __nv_bfloat16 g_Ql[BATCH * SEQ * DH];
__device__ __nv_bfloat16 g_Kh[BATCH * SEQ * DH];
__device__ __nv_bfloat16 g_Kl[BATCH * SEQ * DH];
__device__ __nv_bfloat16 g_Vth[BATCH * DH * SEQ];  // transposed: [b][d][s]
__device__ __nv_bfloat16 g_Vtl[BATCH * DH * SEQ];
// W transposed+split: [mat][n][k] bf16
__device__ __nv_bfloat16 g_Wh[3 * DH * DIN];
__device__ __nv_bfloat16 g_Wl[3 * DH * DIN];
// split-KV accumulators (additive softmax partials)
__device__ float g_Oacc[BATCH * SEQ * DH];
__device__ float g_l[BATCH * SEQ];

__device__ __forceinline__ u32 smem_u32(const void* p) {
    u32 a;
    asm("{ .reg .u64 t; cvta.to.shared.u64 t, %1; cvt.u32.u64 %0, t; }"
        : "=r"(a) : "l"(p));
    return a;
}
__device__ __forceinline__ float ex2f(float x) {
    float r;
    asm("ex2.approx.ftz.f32 %0, %1;" : "=f"(r) : "f"(x));
    return r;
}
__device__ __forceinline__ u32 bfpack(__nv_bfloat16 a, __nv_bfloat16 b) {
    __nv_bfloat162 v; v.x = a; v.y = b;
    return *(u32*)&v;
}
__device__ __forceinline__ u32 packsplit(float x, float y, u32& lo) {
    __nv_bfloat16 hx = __float2bfloat16(x), hy = __float2bfloat16(y);
    lo = bfpack(__float2bfloat16(x - __bfloat162float(hx)),
                __float2bfloat16(y - __bfloat162float(hy)));
    return bfpack(hx, hy);
}
__device__ __forceinline__ void mma_bf16(float c[4], const u32 a[4], u32 b0, u32 b1) {
    asm volatile(
        "mma.sync.aligned.m16n8k16.row.col.f32.bf16.bf16.f32 "
        "{%0,%1,%2,%3}, {%4,%5,%6,%7}, {%8,%9}, {%0,%1,%2,%3};"
        : "+f"(c[0]), "+f"(c[1]), "+f"(c[2]), "+f"(c[3])
        : "r"(a[0]), "r"(a[1]), "r"(a[2]), "r"(a[3]), "r"(b0), "r"(b1));
}
__device__ __forceinline__ void ldm4(u32* r, u32 a) {
    asm volatile("ldmatrix.sync.aligned.m8n8.x4.shared.b16 {%0,%1,%2,%3}, [%4];"
        : "=r"(r[0]), "=r"(r[1]), "=r"(r[2]), "=r"(r[3]) : "r"(a));
}
// L1-enabled async copy (16 B)
__device__ __forceinline__ void cp16(u32 s, const void* g) {
    asm volatile("cp.async.ca.shared.global [%0], [%1], 16;" :: "r"(s), "l"(g) : "memory");
}
#define CP_COMMIT() asm volatile("cp.async.commit_group;" ::: "memory")
#define CP_WAIT(n)  asm volatile("cp.async.wait_group %0;" :: "n"(n) : "memory")

// ---------------------------------------------------------------------------
// split_w: Wt[mat][n][k] bf16 hi/lo from W[k][n] fp32.  grid 192 x 128 thr.
// ---------------------------------------------------------------------------
__global__ void split_w(const float* __restrict__ Wq,
                        const float* __restrict__ Wk,
                        const float* __restrict__ Wv) {
    const int mat = blockIdx.x >> 6;
    const int n   = blockIdx.x & 63;
    const float* W = (mat == 0) ? Wq : (mat == 1) ? Wk : Wv;
    const int k0 = threadIdx.x * 8;
    u32 h[4], l[4];
#pragma unroll
    for (int i = 0; i < 4; i++) {
        float a = W[(k0 + 2 * i) * DH + n];
        float c = W[(k0 + 2 * i + 1) * DH + n];
        h[i] = packsplit(a, c, l[i]);
    }
    const size_t idx = ((size_t)(mat * DH + n) * DIN + k0) / 2;
    *(uint4*)((u32*)g_Wh + idx) = *(uint4*)h;
    *(uint4*)((u32*)g_Wl + idx) = *(uint4*)l;
}

// ---------------------------------------------------------------------------
// zero_acc: clear split-KV accumulators. 2048 x 512.
// ---------------------------------------------------------------------------
__global__ void zero_acc() {
    const int i = blockIdx.x * 512 + threadIdx.x;
    if (i < BATCH * SEQ * DH) g_Oacc[i] = 0.f;
    if (i < BATCH * SEQ)      g_l[i]    = 0.f;
}

// ---------------------------------------------------------------------------
// normalize: O = g_Oacc / g_l (row-wise). 1024 x 256, one float4 per thread.
// ---------------------------------------------------------------------------
__global__ void normalize(float* __restrict__ O) {
    const int i = blockIdx.x * 256 + threadIdx.x;   // float4 index
    float4 v = ((const float4*)g_Oacc)[i];
    const float inv = 1.f / g_l[i >> 4];
    v.x *= inv; v.y *= inv; v.z *= inv; v.w *= inv;
    ((float4*)O)[i] = v;
}

// ---------------------------------------------------------------------------
// qkv_fused: one pass over X computes Q, K, V projections. grid 128 x 256 thr
// (one CTA per 128-row band, single wave). Per k-chunk: X tile loaded+split
// ONCE, then mat loop {W tile load, 24 MMA/warp} fully unrolled into three
// static accumulator sets o[3][8][4]. Epilogues identical to the proven R11
// versions (Q pre-scaled, K direct, V smem-bounce transpose).
// smem 48 KB: Xh(16K) Xl(16K) Wth(8K) Wtl(8K); fb[128][68] reuses it for V.
// ---------------------------------------------------------------------------
__global__ __launch_bounds__(256, 1) void qkv_fused(const float* __restrict__ X) {
    __shared__ u32 sm[12288];
    const u32 sb0 = smem_u32(sm);

    const int tid   = threadIdx.x;
    const int w     = tid >> 5;
    const int lane  = tid & 31;
    const int lane7 = lane & 7;
    const int g     = lane >> 2;
    const int t4    = lane & 3;
    const int row0  = blockIdx.x * 128;

    float o[3][8][4];
#pragma unroll
    for (int m = 0; m < 3; m++)
#pragma unroll
        for (int nb = 0; nb < 8; nb++)
#pragma unroll
            for (int e = 0; e < 4; e++) o[m][nb][e] = 0.f;

    for (int kc = 0; kc < 16; kc++) {
        const int k0 = kc * 64;

        // ---- Load X tile 128x64 fp32, split -> Xh/Xl (swizzled bf16), once ----
#pragma unroll
        for (int i = 0; i < 4; i++) {
            const int ci = tid + 256 * i;
            const int r = ci >> 3, c = ci & 7;
            const float* xs = X + (size_t)(row0 + r) * DIN + k0 + c * 8;
            float4 v0 = *(const float4*)xs;
            float4 v1 = *(const float4*)(xs + 4);
            u32 h[4], l[4];
            h[0] = packsplit(v0.x, v0.y, l[0]);
            h[1] = packsplit(v0.z, v0.w, l[1]);
            h[2] = packsplit(v1.x, v1.y, l[2]);
            h[3] = packsplit(v1.z, v1.w, l[3]);
            const int off = r * 32 + ((c ^ (r & 7)) << 2);
            *(uint4*)(sm + off)        = *(uint4*)h;
            *(uint4*)(sm + 4096 + off) = *(uint4*)l;
        }

        u32 ah[4][4], al[4][4];

#pragma unroll
        for (int mat = 0; mat < 3; mat++) {
            // ---- Load this mat's Wt tile 64x64 bf16 (already split) ----
#pragma unroll
            for (int i = 0; i < 2; i++) {
                const int ci = tid + 256 * i;
                const int n = ci >> 3, c = ci & 7;
                const size_t gsrc = ((size_t)(mat * DH + n) * DIN + k0) / 2 + c * 4;
                uint4 vh = *(const uint4*)((const u32*)g_Wh + gsrc);
                uint4 vl = *(const uint4*)((const u32*)g_Wl + gsrc);
                const int off = n * 32 + ((c ^ (n & 7)) << 2);
                *(uint4*)(sm + 8192 + off)  = vh;
                *(uint4*)(sm + 10240 + off) = vl;
            }
            __syncthreads();

            // ---- Extract X A-fragments once per kc (after first sync) ----
            if (mat == 0) {
                const int m  = lane >> 3, rr = lane & 7;
                const int xrow = 16 * w + rr + 8 * (m & 1);
                const u32 xbh = sb0 + (u32)(xrow * 128);
                const u32 xbl = sb0 + 16384u + (u32)(xrow * 128);
#pragma unroll
                for (int ks = 0; ks < 4; ks++) {
                    const u32 off = (u32)(((2 * ks + (m >> 1)) ^ rr) << 4);
                    ldm4(ah[ks], xbh + off);
                    ldm4(al[ks], xbl + off);
                }
            }

            // ---- MMAs (XhWh + XlWh + XhWl) ----
            const u32 bWh = sb0 + 32768u + (u32)(lane * 128);
            const u32 bWl = sb0 + 40960u + (u32)(lane * 128);
#pragma unroll
            for (int ks = 0; ks < 4; ks++) {
                const u32 c0 = (u32)(((2 * ks)     ^ lane7) << 4);
                const u32 c1 = (u32)(((2 * ks + 1) ^ lane7) << 4);
                u32 f[16];
                ldm4(f,      bWh + c0);
                ldm4(f + 4,  bWh + c1);
                ldm4(f + 8,  bWh + 4096 + c0);
                ldm4(f + 12, bWh + 4096 + c1);
#pragma unroll
                for (int nb = 0; nb < 4; nb++) {
                    mma_bf16(o[mat][nb],     ah[ks], f[nb],     f[4 + nb]);
                    mma_bf16(o[mat][nb],     al[ks], f[nb],     f[4 + nb]);
                    mma_bf16(o[mat][4 + nb], ah[ks], f[8 + nb], f[12 + nb]);
                    mma_bf16(o[mat][4 + nb], al[ks], f[8 + nb], f[12 + nb]);
                }
                u32 gf[16];
                ldm4(gf,      bWl + c0);
                ldm4(gf + 4,  bWl + c1);
                ldm4(gf + 8,  bWl + 4096 + c0);
                ldm4(gf + 12, bWl + 4096 + c1);
#pragma unroll
                for (int nb = 0; nb < 4; nb++) {
                    mma_bf16(o[mat][nb],     ah[ks], gf[nb],     gf[4 + nb]);
                    mma_bf16(o[mat][4 + nb], ah[ks], gf[8 + nb], gf[12 + nb]);
                }
            }
            __syncthreads();   // W buffer (and, on mat==2, X) free for reuse
        }
    }

    // ---- Epilogue: Q (pre-scaled) and K direct split-store ----
    {
        const float qs = 0.125f * 1.44269504088896340736f;
        const int ra = row0 + 16 * w + g;
        const int rb = ra + 8;
#pragma unroll
        for (int nb = 0; nb < 8; nb++) {
            u32 lo, h;
            h = packsplit(o[0][nb][0] * qs, o[0][nb][1] * qs, lo);
            ((u32*)g_Qh)[(size_t)ra * 32 + 4 * nb + t4] = h;
            ((u32*)g_Ql)[(size_t)ra * 32 + 4 * nb + t4] = lo;
            h = packsplit(o[0][nb][2] * qs, o[0][nb][3] * qs, lo);
            ((u32*)g_Qh)[(size_t)rb * 32 + 4 * nb + t4] = h;
            ((u32*)g_Ql)[(size_t)rb * 32 + 4 * nb + t4] = lo;

            h = packsplit(o[1][nb][0], o[1][nb][1], lo);
            ((u32*)g_Kh)[(size_t)ra * 32 + 4 * nb + t4] = h;
            ((u32*)g_Kl)[(size_t)ra * 32 + 4 * nb + t4] = lo;
            h = packsplit(o[1][nb][2], o[1][nb][3], lo);
            ((u32*)g_Kh)[(size_t)rb * 32 + 4 * nb + t4] = h;
            ((u32*)g_Kl)[(size_t)rb * 32 + 4 * nb + t4] = lo;
        }
    }

    // ---- V: bounce through smem to transpose into [b][d][s] ----
    __syncthreads();   // done with MMA smem before fb overwrites it
    {
        float* fb = (float*)sm;              // [128][68]
        const int la = 16 * w + g, lb = la + 8;
#pragma unroll
        for (int nb = 0; nb < 8; nb++) {
            const int col = 8 * nb + 2 * t4;
            fb[la * 68 + col]     = o[2][nb][0];
            fb[la * 68 + col + 1] = o[2][nb][1];
            fb[lb * 68 + col]     = o[2][nb][2];
            fb[lb * 68 + col + 1] = o[2][nb][3];
        }
        __syncthreads();
        const int d    = tid & 63;
        const int tl0  = (tid >> 6) * 32;
        const int b    = row0 >> 12;
        const int tok0 = (row0 & (SEQ - 1)) + tl0;
        u32* H = (u32*)g_Vth;
        u32* L = (u32*)g_Vtl;
        const size_t base = ((size_t)b * 64 + d) * (SEQ / 2) + (tok0 >> 1);
#pragma unroll
        for (int p = 0; p < 16; p++) {
            float a = fb[(tl0 + 2 * p) * 68 + d];
            float c = fb[(tl0 + 2 * p + 1) * 68 + d];
            u32 lo;
            u32 h = packsplit(a, c, lo);
            H[base + p] = h;
            L[base + p] = lo;
        }
    }
}

// ---------------------------------------------------------------------------
// cp.async prefetch of one kv tile into buffer set (t&1)*4 + w.
// ---------------------------------------------------------------------------
__device__ __forceinline__ void prefetch_tile(int t, int b, int w, int lane, u32 sb0) {
    const int j0 = t * 64;
    const u32* src; size_t rstride;
    if (w == 0)      { src = (const u32*)g_Kh  + ((size_t)b * SEQ + j0) * 32; rstride = 32; }
    else if (w == 1) { src = (const u32*)g_Kl  + ((size_t)b * SEQ + j0) * 32; rstride = 32; }
    else if (w == 2) { src = (const u32*)g_Vth + (size_t)b * 64 * (SEQ / 2) + j0 / 2; rstride = SEQ / 2; }
    else             { src = (const u32*)g_Vtl + (size_t)b * 64 * (SEQ / 2) + j0 / 2; rstride = SEQ / 2; }
    const u32 dst = sb0 + (u32)(((t & 1) * 4 + w) * 8192);
#pragma unroll
    for (int rr = 0; rr < 2; rr++) {
        const int r = lane * 2 + rr;
        const u32* s = src + (size_t)r * rstride;
        const u32 da = dst + (u32)(r * 128);
        const int sw = r & 7;
#pragma unroll
        for (int c = 0; c < 8; c++)
            cp16(da + (u32)((c ^ sw) << 4), s + c * 4);
    }
    CP_COMMIT();
}

// ---------------------------------------------------------------------------
// Split-KV HMMA flash attention, LPT schedule, double-buffered cp.async.ca
// K/V prefetch — UNCHANGED from R16 (proven, 146.5 us).
// ---------------------------------------------------------------------------
__global__ __launch_bounds__(128, 3) void flash_attn_mma() {
    extern __shared__ __align__(16) u32 sdyn[];
    const u32 sb0 = smem_u32(sdyn);

    // bid -> (batch, qt, chunk), longest-first (LPT)
    const int bid = blockIdx.x;
    const int b   = bid & 3;
    const int id  = 159 - (bid >> 2);
    int qt, ch;
    if (id < 16)      { qt = id; ch = 0; }
    else if (id < 48) { int k = id - 16; qt = 16 + (k >> 1); ch = k & 1; }
    else if (id < 96) { int k = id - 48; qt = 32 + k / 3;    ch = k - (k / 3) * 3; }
    else              { int k = id - 96; qt = 48 + (k >> 2); ch = k & 3; }
    const int tA = ch * 16;                 // always even
    const int tB = min(tA + 16, qt + 1);

    const int tid   = threadIdx.x;
    const int w     = tid >> 5;
    const int lane  = tid & 31;
    const int lane7 = lane & 7;
    const int g     = lane >> 2;
    const int t4    = lane & 3;
    const int i0    = qt * 64;

    // ---- Prefetch first kv tile (set 0) ----
    prefetch_tile(tA, b, w, lane, sb0);

    // ---- Stage Q (hi/lo) into buffers 4,5 (set 1, free until tile tA+1) ----
    if (w < 2) {
        const u32* src = (const u32*)(w == 0 ? g_Qh : g_Ql) + (size_t)(b * SEQ + i0) * 32;
        u32* dst = sdyn + (4 + w) * 2048;
#pragma unroll
        for (int rr = 0; rr < 2; rr++) {
            const int r = lane * 2 + rr;
            const u32* s = src + r * 32;
#pragma unroll
            for (int c = 0; c < 8; c++)
                *(uint4*)(dst + r * 32 + ((c ^ (r & 7)) << 2)) = *(const uint4*)(s + c * 4);
        }
    }
    __syncthreads();

    // ---- Extract Q A-fragments via ldmatrix ----
    u32 qh[4][4], ql[4][4];
    {
        const int m  = lane >> 3, rr = lane & 7;
        const int qrow = 16 * w + rr + 8 * (m & 1);
        const u32 qbh = sb0 + 4u * 8192 + (u32)(qrow * 128);
        const u32 qbl = sb0 + 5u * 8192 + (u32)(qrow * 128);
#pragma unroll
        for (int ks = 0; ks < 4; ks++) {
            const u32 off = (u32)(((2 * ks + (m >> 1)) ^ rr) << 4);
            ldm4(qh[ks], qbh + off);
            ldm4(ql[ks], qbl + off);
        }
    }
    __syncthreads();   // Q fully extracted before set 1 is overwritten

    float o[8][4];
#pragma unroll
    for (int nb = 0; nb < 8; nb++)
#pragma unroll
        for (int e = 0; e < 4; e++) o[nb][e] = 0.f;
    float lacc0 = 0.f, lacc1 = 0.f;

    const u32 rowoff = (u32)(lane * 128);

    for (int t = tA; t < tB; t++) {
        const int j0 = t * 64;

        if (t + 1 < tB) {
            prefetch_tile(t + 1, b, w, lane, sb0);
            CP_WAIT(1);
        } else {
            CP_WAIT(0);
        }
        __syncthreads();

        const u32 base = sb0 + (u32)((t & 1) * 4 * 8192);
        const u32 bKh = base + rowoff;
        const u32 bKl = base + 8192u + rowoff;
        const u32 bVh = base + 16384u + rowoff;
        const u32 bVl = base + 24576u + rowoff;

        // ---- S = Qh·Kh + Ql·Kh + Qh·Kl ----
        float s[8][4];
#pragma unroll
        for (int nb = 0; nb < 8; nb++)
#pragma unroll
            for (int e = 0; e < 4; e++) s[nb][e] = 0.f;

#pragma unroll
        for (int ks = 0; ks < 4; ks++) {
            const u32 c0 = (u32)(((2 * ks)     ^ lane7) << 4);
            const u32 c1 = (u32)(((2 * ks + 1) ^ lane7) << 4);
            u32 f[16];
            ldm4(f,      bKh + c0);
            ldm4(f + 4,  bKh + c1);
            ldm4(f + 8,  bKh + 4096 + c0);
            ldm4(f + 12, bKh + 4096 + c1);
#pragma unroll
            for (int nb = 0; nb < 4; nb++) {
                mma_bf16(s[nb],     qh[ks], f[nb],     f[4 + nb]);
                mma_bf16(s[nb],     ql[ks], f[nb],     f[4 + nb]);
                mma_bf16(s[4 + nb], qh[ks], f[8 + nb], f[12 + nb]);
                mma_bf16(s[4 + nb], ql[ks], f[8 + nb], f[12 + nb]);
            }
            u32 gf[16];
            ldm4(gf,      bKl + c0);
            ldm4(gf + 4,  bKl + c1);
            ldm4(gf + 8,  bKl + 4096 + c0);
            ldm4(gf + 12, bKl + 4096 + c1);
#pragma unroll
            for (int nb = 0; nb < 4; nb++) {
                mma_bf16(s[nb],     qh[ks], gf[nb],     gf[4 + nb]);
                mma_bf16(s[4 + nb], qh[ks], gf[8 + nb], gf[12 + nb]);
            }
        }

        // ---- Fixed-max softmax + causal mask on the diagonal tile ----
        const bool diag = (t == qt);
        const int rowa = i0 + 16 * w + g;
        const int rowb = rowa + 8;
#pragma unroll
        for (int nb = 0; nb < 8; nb++) {
            const int colb = j0 + 8 * nb + 2 * t4;
            float p0 = ex2f(s[nb][0]); if (diag && colb     > rowa) p0 = 0.f;
            float p1 = ex2f(s[nb][1]); if (diag && colb + 1 > rowa) p1 = 0.f;
            float p2 = ex2f(s[nb][2]); if (diag && colb     > rowb) p2 = 0.f;
            float p3 = ex2f(s[nb][3]); if (diag && colb + 1 > rowb) p3 = 0.f;
            lacc0 += p0 + p1;
            lacc1 += p2 + p3;
            s[nb][0] = p0; s[nb][1] = p1; s[nb][2] = p2; s[nb][3] = p3;
        }

        // ---- P -> bf16 hi/lo A-fragments ----
        u32 ph[4][4], pl[4][4];
#pragma unroll
        for (int ks = 0; ks < 4; ks++) {
            ph[ks][0] = packsplit(s[2 * ks][0],     s[2 * ks][1],     pl[ks][0]);
            ph[ks][1] = packsplit(s[2 * ks][2],     s[2 * ks][3],     pl[ks][1]);
            ph[ks][2] = packsplit(s[2 * ks + 1][0], s[2 * ks + 1][1], pl[ks][2]);
            ph[ks][3] = packsplit(s[2 * ks + 1][2], s[2 * ks + 1][3], pl[ks][3]);
        }

        // ---- O += Ph·Vh + Pl·Vh + Ph·Vl ----
#pragma unroll
        for (int ks = 0; ks < 4; ks++) {
            const u32 c0 = (u32)(((2 * ks)     ^ lane7) << 4);
            const u32 c1 = (u32)(((2 * ks + 1) ^ lane7) << 4);
            u32 f[16];
            ldm4(f,      bVh + c0);
            ldm4(f + 4,  bVh + c1);
            ldm4(f + 8,  bVh + 4096 + c0);
            ldm4(f + 12, bVh + 4096 + c1);
#pragma unroll
            for (int nb = 0; nb < 4; nb++) {
                mma_bf16(o[nb],     ph[ks], f[nb],     f[4 + nb]);
                mma_bf16(o[nb],     pl[ks], f[nb],     f[4 + nb]);
                mma_bf16(o[4 + nb], ph[ks], f[8 + nb], f[12 + nb]);
                mma_bf16(o[4 + nb], pl[ks], f[8 + nb], f[12 + nb]);
            }
            u32 gf[16];
            ldm4(gf,      bVl + c0);
            ldm4(gf + 4,  bVl + c1);
            ldm4(gf + 8,  bVl + 4096 + c0);
            ldm4(gf + 12, bVl + 4096 + c1);
#pragma unroll
            for (int nb = 0; nb < 4; nb++) {
                mma_bf16(o[nb],     ph[ks], gf[nb],     gf[4 + nb]);
                mma_bf16(o[4 + nb], ph[ks], gf[8 + nb], gf[12 + nb]);
            }
        }
        __syncthreads();
    }

    // ---- Accumulate partials ----
    lacc0 += __shfl_xor_sync(0xffffffffu, lacc0, 1);
    lacc0 += __shfl_xor_sync(0xffffffffu, lacc0, 2);
    lacc1 += __shfl_xor_sync(0xffffffffu, lacc1, 1);
    lacc1 += __shfl_xor_sync(0xffffffffu, lacc1, 2);

    const int rowa = i0 + 16 * w + g;
    if (t4 == 0) {
        atomicAdd(&g_l[(size_t)b * SEQ + rowa],     lacc0);
        atomicAdd(&g_l[(size_t)b * SEQ + rowa + 8], lacc1);
    }

    float* Oa = g_Oacc + ((size_t)b * SEQ + rowa) * 64;
    float* Ob = Oa + 8 * 64;
#pragma unroll
    for (int nb = 0; nb < 8; nb++) {
        const int col = 8 * nb + 2 * t4;
        atomicAdd(Oa + col,     o[nb][0]);
        atomicAdd(Oa + col + 1, o[nb][1]);
        atomicAdd(Ob + col,     o[nb][2]);
        atomicAdd(Ob + col + 1, o[nb][3]);
    }
}

// ---------------------------------------------------------------------------
extern "C" void kernel_launch(void* const* d_in, const int* in_sizes, int n_in,
                              void* d_out, int out_size) {
    const float* X  = (const float*)d_in[0];
    const float* Wq = (const float*)d_in[1];
    const float* Wk = (const float*)d_in[2];
    const float* Wv = (const float*)d_in[3];
    float* O = (float*)d_out;

    static int attr_set = 0;
    if (!attr_set) {
        cudaFuncSetAttribute(flash_attn_mma,
                             cudaFuncAttributeMaxDynamicSharedMemorySize, 65536);
        attr_set = 1;
    }

    zero_acc<<<2048, 512>>>();
    split_w<<<192, 128>>>(Wq, Wk, Wv);
    qkv_fused<<<128, 256>>>(X);
    flash_attn_mma<<<640, 128, 65536>>>();
    normalize<<<1024, 256>>>(O);
}